// round 11
// baseline (speedup 1.0000x reference)
#include <cuda_runtime.h>
#include <math.h>

#define Bsz 4
#define Lseq 4096
#define DIN 256
#define DST 16
#define DTR 8
#define NSEG 16
#define SEGL 256   // Lseq / NSEG

// ---------------- scratch ----------------
__device__ __align__(16) float g_fop[Bsz*Lseq*128];      // (b,l,128)
__device__ __align__(16) float g_xz [Bsz*Lseq*512];      // (b,l,512)
__device__ __align__(16) float g_x  [Bsz*DIN*Lseq];      // post-conv silu, (b,d,l)
__device__ __align__(16) float g_z  [Bsz*DIN*Lseq];      // silu(z) gate, (b,d,l)
__device__ __align__(16) float g_dt [Bsz*DIN*Lseq];      // (b,d,l)
__device__ __align__(16) float g_Bm [Bsz*DST*Lseq];      // (b,n,l)  << transposed
__device__ __align__(16) float g_Cm [Bsz*DST*Lseq];      // (b,n,l)  << transposed
__device__ __align__(16) float g_y  [Bsz*DIN*Lseq];      // (b,d,l)
__device__ __align__(16) float g_residual[Bsz*32*Lseq];  // (b,c,h,w)
__device__ __align__(16) float g_segH[Bsz*DIN*NSEG*DST];
__device__ __align__(16) float g_segP[Bsz*DIN*NSEG*DST];
__device__ __align__(16) float g_h0  [Bsz*DIN*NSEG*DST];
__device__ float g_cmean[Bsz*32];
__device__ float g_scale[Bsz*32];

__device__ __forceinline__ float silu_f(float v) { return v / (1.f + __expf(-v)); }
__device__ __forceinline__ float softplus_f(float v) { return (v > 20.f) ? v : log1pf(__expf(v)); }

// ---------------- K0: gather 4-direction sequence from fo1 ----------------
__global__ void gather_kernel(const float* __restrict__ fo1) {
    int idx = blockIdx.x * 256 + threadIdx.x;            // < 4*4096*128
    int j = idx & 127;
    int l = (idx >> 7) & 4095;
    int b = idx >> 19;
    int g = j >> 5, c = j & 31;
    int l2 = (g & 1) ? (4095 - l) : l;
    int pos = (g < 2) ? l2 : (((l2 & 63) << 6) | (l2 >> 6));
    g_fop[idx] = fo1[((size_t)(b*32 + c))*4096 + pos];
}

// ---------------- K1: xz = fop @ in_w^T, classic FFMA 128x128x16, 8x8/thr ----------------
__global__ void gemm1_kernel(const float* __restrict__ in_w) {
    __shared__ float As[16][132];
    __shared__ float Ws[16][132];
    const int tid = threadIdx.x;
    const int bm = blockIdx.y * 128, bn = blockIdx.x * 128;
    const int tm = (tid >> 4) * 8;
    const int tn = (tid & 15) * 8;
    float acc[8][8];
    #pragma unroll
    for (int i = 0; i < 8; i++)
        #pragma unroll
        for (int j = 0; j < 8; j++) acc[i][j] = 0.f;

    for (int k0 = 0; k0 < 128; k0 += 16) {
        #pragma unroll
        for (int i = tid; i < 2048; i += 256) {
            int m = i >> 4, k = i & 15;
            As[k][m] = g_fop[(size_t)(bm + m)*128 + k0 + k];
        }
        #pragma unroll
        for (int i = tid; i < 2048; i += 256) {
            int n = i >> 4, k = i & 15;
            Ws[k][n] = in_w[(size_t)(bn + n)*128 + k0 + k];
        }
        __syncthreads();
        #pragma unroll
        for (int k = 0; k < 16; k++) {
            float ra[8], rw[8];
            *(float4*)&ra[0] = *(const float4*)&As[k][tm];
            *(float4*)&ra[4] = *(const float4*)&As[k][tm + 4];
            *(float4*)&rw[0] = *(const float4*)&Ws[k][tn];
            *(float4*)&rw[4] = *(const float4*)&Ws[k][tn + 4];
            #pragma unroll
            for (int i = 0; i < 8; i++)
                #pragma unroll
                for (int j = 0; j < 8; j++) acc[i][j] = fmaf(ra[i], rw[j], acc[i][j]);
        }
        __syncthreads();
    }
    #pragma unroll
    for (int i = 0; i < 8; i++) {
        float* cp = &g_xz[(size_t)(bm + tm + i)*512 + bn + tn];
        *(float4*)cp       = make_float4(acc[i][0], acc[i][1], acc[i][2], acc[i][3]);
        *(float4*)(cp + 4) = make_float4(acc[i][4], acc[i][5], acc[i][6], acc[i][7]);
    }
}

// ---------------- K2: causal depthwise conv(4)+bias+silu; z stored as silu(z) gate ----------------
__global__ void conv_transpose_kernel(const float* __restrict__ conv_w, const float* __restrict__ conv_b) {
    int b = blockIdx.z, lt = blockIdx.y, ct = blockIdx.x;
    int c0 = ct * 32;
    int l0 = lt * 32;
    __shared__ float s[35][33];
    for (int i = threadIdx.x; i < 35*32; i += 256) {
        int li = i >> 5, ci = i & 31;
        int l = l0 - 3 + li;
        s[li][ci] = (l >= 0) ? g_xz[((size_t)b*4096 + l)*512 + c0 + ci] : 0.f;
    }
    __syncthreads();
    int li = threadIdx.x & 31;
    int cw0 = threadIdx.x >> 5;
    if (c0 < 256) {
        for (int ci = cw0; ci < 32; ci += 8) {
            int c = c0 + ci;
            float w0 = conv_w[c*4+0], w1 = conv_w[c*4+1], w2 = conv_w[c*4+2], w3 = conv_w[c*4+3];
            float acc = conv_b[c];
            acc = fmaf(w0, s[li][ci], acc);
            acc = fmaf(w1, s[li+1][ci], acc);
            acc = fmaf(w2, s[li+2][ci], acc);
            acc = fmaf(w3, s[li+3][ci], acc);
            g_x[((size_t)(b*256 + c))*4096 + l0 + li] = silu_f(acc);
        }
    } else {
        for (int ci = cw0; ci < 32; ci += 8) {
            int zc = c0 + ci - 256;
            g_z[((size_t)(b*256 + zc))*4096 + l0 + li] = silu_f(s[li+3][ci]);
        }
    }
}

// ---------------- K3: dbl = x @ x_w^T (N=40) -> B,C (transposed) + fused dt projection ----------------
// grid (64 lt, 4 b), block 256.  Block: 64 l x 40 j.  Thread: 2l x 5j.
__global__ void gemm2_kernel(const float* __restrict__ x_w, const float* __restrict__ dt_w,
                             const float* __restrict__ dt_b) {
    const int b = blockIdx.y;
    const int l0 = blockIdx.x * 64;
    __shared__ float xs[32][66];
    __shared__ float ws[40][33];
    __shared__ float sdtr[64][9];
    __shared__ float sdw[256*8];
    __shared__ float sdb[256];
    const int tid = threadIdx.x;
    const int tcol = tid & 31;
    const int trow = tid >> 5;
    float acc[2][5];
    #pragma unroll
    for (int i = 0; i < 2; i++)
        #pragma unroll
        for (int j = 0; j < 5; j++) acc[i][j] = 0.f;

    for (int i = tid; i < 2048; i += 256) sdw[i] = dt_w[i];
    if (tid < 256) sdb[tid] = dt_b[tid];

    for (int k0 = 0; k0 < 256; k0 += 32) {
        #pragma unroll
        for (int i = tid; i < 2048; i += 256) {
            int kk = i >> 6, lx = i & 63;
            xs[kk][lx] = g_x[((size_t)(b*256 + k0 + kk))*4096 + l0 + lx];
        }
        #pragma unroll
        for (int i = tid; i < 1280; i += 256) {
            int j = i >> 5, kk = i & 31;
            ws[j][kk] = x_w[j*256 + k0 + kk];
        }
        __syncthreads();
        #pragma unroll
        for (int kk = 0; kk < 32; kk++) {
            float2 a = *(const float2*)&xs[kk][tcol*2];
            float w[5];
            #pragma unroll
            for (int jj = 0; jj < 5; jj++) w[jj] = ws[trow*5 + jj][kk];
            #pragma unroll
            for (int jj = 0; jj < 5; jj++) {
                acc[0][jj] = fmaf(a.x, w[jj], acc[0][jj]);
                acc[1][jj] = fmaf(a.y, w[jj], acc[1][jj]);
            }
        }
        __syncthreads();
    }
    #pragma unroll
    for (int i = 0; i < 2; i++) {
        int lx = tcol*2 + i;
        int l = l0 + lx;
        #pragma unroll
        for (int jj = 0; jj < 5; jj++) {
            int j = trow*5 + jj;
            float v = acc[i][jj];
            if (j < 8)       sdtr[lx][j] = v;
            else if (j < 24) g_Bm[((size_t)(b*16 + (j - 8)))*4096 + l]  = v;   // (b,n,l)
            else             g_Cm[((size_t)(b*16 + (j - 24)))*4096 + l] = v;   // (b,n,l)
        }
    }
    __syncthreads();
    int lx = tid & 63;
    int dg = tid >> 6;
    float r0 = sdtr[lx][0], r1 = sdtr[lx][1], r2 = sdtr[lx][2], r3 = sdtr[lx][3];
    float r4 = sdtr[lx][4], r5 = sdtr[lx][5], r6 = sdtr[lx][6], r7 = sdtr[lx][7];
    #pragma unroll 4
    for (int dd = 0; dd < 64; dd++) {
        int d = dg*64 + dd;
        const float* w = &sdw[d*8];
        float a = sdb[d];
        a = fmaf(r0, w[0], a); a = fmaf(r1, w[1], a);
        a = fmaf(r2, w[2], a); a = fmaf(r3, w[3], a);
        a = fmaf(r4, w[4], a); a = fmaf(r5, w[5], a);
        a = fmaf(r6, w[6], a); a = fmaf(r7, w[7], a);
        g_dt[((size_t)(b*256 + d))*4096 + l0 + lx] = softplus_f(a);
    }
}

// ---------------- K5a: scan pass A — per-segment decay product + end state ----------------
__global__ void scanA_kernel(const float* __restrict__ A_log) {
    int tid = threadIdx.x;
    int n = tid & 15;
    int task = blockIdx.x * 16 + (tid >> 4);   // 0..16383
    int chain = task >> 4;                     // b*256+d
    int s = task & 15;
    int b = chain >> 8, d = chain & 255;
    int l0 = s * SEGL;
    const float* dtp = g_dt + (size_t)chain*4096 + l0;
    const float* xp  = g_x  + (size_t)chain*4096 + l0;
    const float* Bp  = g_Bm + ((size_t)(b*16 + n))*4096 + l0;   // contiguous in l
    float An = -__expf(A_log[d*16 + n]);
    float h = 0.f, P = 1.f;
    for (int l = 0; l < SEGL; l += 4) {
        float4 dt4 = *(const float4*)(dtp + l);
        float4 x4  = *(const float4*)(xp  + l);
        float4 B4  = *(const float4*)(Bp  + l);
        float dta[4] = {dt4.x, dt4.y, dt4.z, dt4.w};
        float xa [4] = {x4.x,  x4.y,  x4.z,  x4.w};
        float Ba [4] = {B4.x,  B4.y,  B4.z,  B4.w};
        #pragma unroll
        for (int i = 0; i < 4; i++) {
            float dt = dta[i];
            float dA = __expf(dt * An);
            P *= dA;
            h = fmaf(dA, h, dt * xa[i] * Ba[i]);
        }
    }
    g_segH[task*16 + n] = h;
    g_segP[task*16 + n] = P;
}

// ---------------- K5b: combine — prefix over segments per (chain, n); zero cmean ----------------
__global__ void scanC_kernel() {
    int t = blockIdx.x * 256 + threadIdx.x;    // 16384
    if (t < 128) g_cmean[t] = 0.f;
    int chain = t >> 4, n = t & 15;
    float h = 0.f;
    #pragma unroll
    for (int s = 0; s < NSEG; s++) {
        int idx = (chain*16 + s)*16 + n;
        g_h0[idx] = h;
        h = g_segH[idx] + g_segP[idx]*h;
    }
}

// ---------------- K5c: scan pass B — outputs, y in (b,d,l) layout ----------------
__global__ void scanB_kernel(const float* __restrict__ A_log, const float* __restrict__ Dp) {
    int tid = threadIdx.x;
    int n = tid & 15;
    int task = blockIdx.x * 16 + (tid >> 4);
    int chain = task >> 4;
    int s = task & 15;
    int b = chain >> 8, d = chain & 255;
    int l0 = s * SEGL;
    const float* dtp = g_dt + (size_t)chain*4096 + l0;
    const float* xp  = g_x  + (size_t)chain*4096 + l0;
    const float* zp  = g_z  + (size_t)chain*4096 + l0;   // pre-gated silu(z)
    const float* Bp  = g_Bm + ((size_t)(b*16 + n))*4096 + l0;
    const float* Cp  = g_Cm + ((size_t)(b*16 + n))*4096 + l0;
    float* yout = g_y + (size_t)chain*4096 + l0;
    float An = -__expf(A_log[d*16 + n]);
    float Dd = Dp[d];
    float h = g_h0[task*16 + n];
    for (int l = 0; l < SEGL; l += 4) {
        float4 dt4 = *(const float4*)(dtp + l);
        float4 x4  = *(const float4*)(xp  + l);
        float4 z4  = *(const float4*)(zp  + l);
        float4 B4  = *(const float4*)(Bp  + l);
        float4 C4  = *(const float4*)(Cp  + l);
        float dta[4] = {dt4.x, dt4.y, dt4.z, dt4.w};
        float xa [4] = {x4.x,  x4.y,  x4.z,  x4.w};
        float ga [4] = {z4.x,  z4.y,  z4.z,  z4.w};
        float Ba [4] = {B4.x,  B4.y,  B4.z,  B4.w};
        float Ca [4] = {C4.x,  C4.y,  C4.z,  C4.w};
        float ov[4];
        #pragma unroll
        for (int i = 0; i < 4; i++) {
            float dt = dta[i];
            float dA = __expf(dt * An);
            h = fmaf(dA, h, dt * xa[i] * Ba[i]);
            float y = h * Ca[i];
            y += __shfl_xor_sync(0xFFFFFFFFu, y, 8);
            y += __shfl_xor_sync(0xFFFFFFFFu, y, 4);
            y += __shfl_xor_sync(0xFFFFFFFFu, y, 2);
            y += __shfl_xor_sync(0xFFFFFFFFu, y, 1);
            ov[i] = fmaf(xa[i], Dd, y) * ga[i];
        }
        if (n == 0) {
            *(float4*)(yout + l) = make_float4(ov[0], ov[1], ov[2], ov[3]);
        }
    }
}

// ---------------- K7: res[b,c,l] = (sum_d y[b,d,l]*wsum[c,d]) * fo2[b,c,l]; cmean atomics ----------------
__global__ void gemm3t_kernel(const float* __restrict__ fo2, const float* __restrict__ out_w) {
    int b = blockIdx.x >> 5, lt = blockIdx.x & 31;
    int l0 = lt * 128;
    __shared__ float xs[16][128];
    __shared__ float ws[32][17];
    int tid = threadIdx.x;
    int ll = tid & 127, jg = tid >> 7;
    int lane = tid & 31;
    float acc[16];
    #pragma unroll
    for (int j = 0; j < 16; j++) acc[j] = 0.f;

    for (int k0 = 0; k0 < 256; k0 += 16) {
        for (int i = tid; i < 16*128; i += 256) {
            int di = i >> 7, lix = i & 127;
            xs[di][lix] = g_y[((size_t)(b*256 + k0 + di))*4096 + l0 + lix];
        }
        for (int i = tid; i < 32*16; i += 256) {
            int j = i / 16, kk = i % 16;
            int col = k0 + kk;
            ws[j][kk] = out_w[j*256 + col] + out_w[(32 + j)*256 + col]
                      + out_w[(64 + j)*256 + col] + out_w[(96 + j)*256 + col];
        }
        __syncthreads();
        #pragma unroll
        for (int di = 0; di < 16; di++) {
            float a = xs[di][ll];
            #pragma unroll
            for (int jj = 0; jj < 16; jj++)
                acc[jj] = fmaf(a, ws[jg*16 + jj][di], acc[jj]);
        }
        __syncthreads();
    }
    int l = l0 + ll;
    #pragma unroll
    for (int jj = 0; jj < 16; jj++) {
        int c = jg*16 + jj;
        size_t idx = ((size_t)(b*32 + c))*4096 + l;
        float r = acc[jj] * fo2[idx];
        g_residual[idx] = r;
        float s = r;
        s += __shfl_xor_sync(0xFFFFFFFFu, s, 16);
        s += __shfl_xor_sync(0xFFFFFFFFu, s, 8);
        s += __shfl_xor_sync(0xFFFFFFFFu, s, 4);
        s += __shfl_xor_sync(0xFFFFFFFFu, s, 2);
        s += __shfl_xor_sync(0xFFFFFFFFu, s, 1);
        if (lane == 0) atomicAdd(&g_cmean[b*32 + c], s);
    }
}

// ---------------- K9: entire tiny mamba2, one block ----------------
__global__ void mamba2_kernel(const float* __restrict__ in_w, const float* __restrict__ conv_w,
                              const float* __restrict__ conv_b, const float* __restrict__ x_w,
                              const float* __restrict__ dt_w, const float* __restrict__ dt_b,
                              const float* __restrict__ A_log, const float* __restrict__ Dp,
                              const float* __restrict__ out_w) {
    __shared__ float sxp[4][32][4];
    __shared__ float sx [4][32][4];
    __shared__ float sz [4][32][4];
    __shared__ float sdt[4][32][4];
    __shared__ float sB [4][32][16];
    __shared__ float sC [4][32][16];
    __shared__ float sy [4][32][4];
    int tid = threadIdx.x;
    int b = tid >> 5, l = tid & 31;
    float m0 = g_cmean[b*32 + l] * (1.f/4096.f);
    float m1 = g_cmean[b*32 + 31 - l] * (1.f/4096.f);
    #pragma unroll
    for (int j = 0; j < 4; j++) {
        sxp[b][l][j] = m0*in_w[j*2]       + m1*in_w[j*2 + 1];
        sz [b][l][j] = m0*in_w[(j+4)*2]   + m1*in_w[(j+4)*2 + 1];
    }
    __syncthreads();
    #pragma unroll
    for (int c = 0; c < 4; c++) {
        float acc = conv_b[c];
        #pragma unroll
        for (int t = 0; t < 4; t++) {
            int ls = l - 3 + t;
            float v = (ls >= 0) ? sxp[b][ls][c] : 0.f;
            acc = fmaf(conv_w[c*4 + t], v, acc);
        }
        sx[b][l][c] = acc / (1.f + expf(-acc));
    }
    __syncthreads();
    {
        float xv[4] = {sx[b][l][0], sx[b][l][1], sx[b][l][2], sx[b][l][3]};
        float dtr = 0.f;
        #pragma unroll
        for (int c = 0; c < 4; c++) dtr = fmaf(xv[c], x_w[c], dtr);
        #pragma unroll
        for (int n = 0; n < 16; n++) {
            float bb = 0.f, cc = 0.f;
            #pragma unroll
            for (int c = 0; c < 4; c++) {
                bb = fmaf(xv[c], x_w[(1 + n)*4 + c], bb);
                cc = fmaf(xv[c], x_w[(17 + n)*4 + c], cc);
            }
            sB[b][l][n] = bb;
            sC[b][l][n] = cc;
        }
        #pragma unroll
        for (int dd = 0; dd < 4; dd++) {
            float a = fmaf(dtr, dt_w[dd], dt_b[dd]);
            sdt[b][l][dd] = (a > 20.f) ? a : log1pf(expf(a));
        }
    }
    __syncthreads();
    {
        int lane = tid & 31, wb = tid >> 5;
        int grp = lane >> 4, n = lane & 15;
        int d0 = grp, d1 = grp + 2;
        float A0 = -expf(A_log[d0*16 + n]);
        float A1 = -expf(A_log[d1*16 + n]);
        float h0 = 0.f, h1 = 0.f;
        for (int t = 0; t < 32; t++) {
            float Bv = sB[wb][t][n], Cv = sC[wb][t][n];
            float dt0 = sdt[wb][t][d0], x0 = sx[wb][t][d0];
            float dt1 = sdt[wb][t][d1], x1 = sx[wb][t][d1];
            h0 = fmaf(__expf(dt0*A0), h0, dt0*x0*Bv);
            h1 = fmaf(__expf(dt1*A1), h1, dt1*x1*Bv);
            float y0 = h0*Cv, y1 = h1*Cv;
            y0 += __shfl_xor_sync(0xFFFFFFFFu, y0, 8);
            y0 += __shfl_xor_sync(0xFFFFFFFFu, y0, 4);
            y0 += __shfl_xor_sync(0xFFFFFFFFu, y0, 2);
            y0 += __shfl_xor_sync(0xFFFFFFFFu, y0, 1);
            y1 += __shfl_xor_sync(0xFFFFFFFFu, y1, 8);
            y1 += __shfl_xor_sync(0xFFFFFFFFu, y1, 4);
            y1 += __shfl_xor_sync(0xFFFFFFFFu, y1, 2);
            y1 += __shfl_xor_sync(0xFFFFFFFFu, y1, 1);
            if (n == 0) { sy[wb][t][d0] = y0; sy[wb][t][d1] = y1; }
        }
    }
    __syncthreads();
    {
        float scale = 0.f;
        #pragma unroll
        for (int dd = 0; dd < 4; dd++) {
            float yv = fmaf(sx[b][l][dd], Dp[dd], sy[b][l][dd]);
            float zz = sz[b][l][dd];
            yv *= zz / (1.f + expf(-zz));
            scale = fmaf(yv, out_w[dd] + out_w[4 + dd], scale);
        }
        g_scale[b*32 + l] = scale;
    }
}

// ---------------- K10: out = residual * (scale + 1) ----------------
__global__ void final_kernel(float* __restrict__ out) {
    int idx = blockIdx.x * 256 + threadIdx.x;
    out[idx] = g_residual[idx] * (g_scale[idx >> 12] + 1.f);
}

// ---------------- launch ----------------
extern "C" void kernel_launch(void* const* d_in, const int* in_sizes, int n_in,
                              void* d_out, int out_size) {
    const float* fo1      = (const float*)d_in[0];
    const float* fo2      = (const float*)d_in[1];
    const float* m1_in_w  = (const float*)d_in[2];
    const float* m1_conv_w= (const float*)d_in[3];
    const float* m1_conv_b= (const float*)d_in[4];
    const float* m1_x_w   = (const float*)d_in[5];
    const float* m1_dt_w  = (const float*)d_in[6];
    const float* m1_dt_b  = (const float*)d_in[7];
    const float* m1_A_log = (const float*)d_in[8];
    const float* m1_D     = (const float*)d_in[9];
    const float* m1_out_w = (const float*)d_in[10];
    const float* m2_in_w  = (const float*)d_in[11];
    const float* m2_conv_w= (const float*)d_in[12];
    const float* m2_conv_b= (const float*)d_in[13];
    const float* m2_x_w   = (const float*)d_in[14];
    const float* m2_dt_w  = (const float*)d_in[15];
    const float* m2_dt_b  = (const float*)d_in[16];
    const float* m2_A_log = (const float*)d_in[17];
    const float* m2_D     = (const float*)d_in[18];
    const float* m2_out_w = (const float*)d_in[19];
    float* out = (float*)d_out;

    gather_kernel<<<8192, 256>>>(fo1);
    gemm1_kernel<<<dim3(4, 128), 256>>>(m1_in_w);
    conv_transpose_kernel<<<dim3(16, 128, 4), 256>>>(m1_conv_w, m1_conv_b);
    gemm2_kernel<<<dim3(64, 4), 256>>>(m1_x_w, m1_dt_w, m1_dt_b);
    scanA_kernel<<<1024, 256>>>(m1_A_log);
    scanC_kernel<<<64, 256>>>();
    scanB_kernel<<<1024, 256>>>(m1_A_log, m1_D);
    gemm3t_kernel<<<128, 256>>>(fo2, m1_out_w);
    mamba2_kernel<<<1, 128>>>(m2_in_w, m2_conv_w, m2_conv_b, m2_x_w, m2_dt_w,
                              m2_dt_b, m2_A_log, m2_D, m2_out_w);
    final_kernel<<<2048, 256>>>(out);
}

// round 12
// speedup vs baseline: 1.3984x; 1.3984x over previous
#include <cuda_runtime.h>
#include <math.h>

#define Bsz 4
#define Lseq 4096
#define DIN 256
#define DST 16
#define DTR 8
#define NSEG 16
#define SEGL 256   // Lseq / NSEG

// ---------------- scratch ----------------
__device__ __align__(16) float g_xz [Bsz*Lseq*512];      // (b,l,512)
__device__ __align__(16) float g_x  [Bsz*DIN*Lseq];      // post-conv silu, (b,d,l)
__device__ __align__(16) float g_z  [Bsz*DIN*Lseq];      // silu(z) gate, (b,d,l)
__device__ __align__(16) float g_dt [Bsz*DIN*Lseq];      // (b,d,l)
__device__ __align__(16) float g_Bm [Bsz*Lseq*DST];      // (b,l,16)
__device__ __align__(16) float g_Cm [Bsz*Lseq*DST];      // (b,l,16)
__device__ __align__(16) float g_y  [Bsz*DIN*Lseq];      // (b,d,l)
__device__ __align__(16) float g_residual[Bsz*32*Lseq];  // (b,c,h,w)
__device__ __align__(16) float g_segH[Bsz*DIN*NSEG*DST];
__device__ __align__(16) float g_segP[Bsz*DIN*NSEG*DST];
__device__ __align__(16) float g_h0  [Bsz*DIN*NSEG*DST];
__device__ float g_cmean[Bsz*32];
__device__ float g_scale[Bsz*32];

__device__ __forceinline__ float silu_f(float v) { return v / (1.f + __expf(-v)); }
__device__ __forceinline__ float softplus_f(float v) { return (v > 20.f) ? v : log1pf(__expf(v)); }

// ---------------- K1: xz = fop @ in_w^T, FFMA 128x128x16, 8x8/thr, gather fused in A-load ----------------
__global__ void gemm1_kernel(const float* __restrict__ fo1, const float* __restrict__ in_w) {
    __shared__ float As[16][132];
    __shared__ float Ws[16][132];
    const int tid = threadIdx.x;
    const int bm = blockIdx.y * 128, bn = blockIdx.x * 128;
    const int tm = (tid >> 4) * 8;
    const int tn = (tid & 15) * 8;
    const int b = bm >> 12;
    float acc[8][8];
    #pragma unroll
    for (int i = 0; i < 8; i++)
        #pragma unroll
        for (int j = 0; j < 8; j++) acc[i][j] = 0.f;

    for (int k0 = 0; k0 < 128; k0 += 16) {
        // A-tile: gather fop[bm+m][k0+kk] directly from fo1
        #pragma unroll
        for (int it = 0; it < 8; it++) {
            int i = tid + it*256;
            int m = i & 127, kk = i >> 7;
            int j = k0 + kk;                 // channel index 0..127
            int g = j >> 5, c = j & 31;
            int l = (bm + m) & 4095;
            int l2 = (g & 1) ? 4095 - l : l;
            int pos = (g < 2) ? l2 : (((l2 & 63) << 6) | (l2 >> 6));
            As[kk][m] = fo1[((size_t)(b*32 + c))*4096 + pos];
        }
        #pragma unroll
        for (int i = tid; i < 2048; i += 256) {
            int n = i >> 4, k = i & 15;
            Ws[k][n] = in_w[(size_t)(bn + n)*128 + k0 + k];
        }
        __syncthreads();
        #pragma unroll
        for (int k = 0; k < 16; k++) {
            float ra[8], rw[8];
            *(float4*)&ra[0] = *(const float4*)&As[k][tm];
            *(float4*)&ra[4] = *(const float4*)&As[k][tm + 4];
            *(float4*)&rw[0] = *(const float4*)&Ws[k][tn];
            *(float4*)&rw[4] = *(const float4*)&Ws[k][tn + 4];
            #pragma unroll
            for (int i = 0; i < 8; i++)
                #pragma unroll
                for (int j = 0; j < 8; j++) acc[i][j] = fmaf(ra[i], rw[j], acc[i][j]);
        }
        __syncthreads();
    }
    #pragma unroll
    for (int i = 0; i < 8; i++) {
        float* cp = &g_xz[(size_t)(bm + tm + i)*512 + bn + tn];
        *(float4*)cp       = make_float4(acc[i][0], acc[i][1], acc[i][2], acc[i][3]);
        *(float4*)(cp + 4) = make_float4(acc[i][4], acc[i][5], acc[i][6], acc[i][7]);
    }
}

// ---------------- K2: causal depthwise conv(4)+bias+silu; z stored as silu(z) gate ----------------
__global__ void conv_transpose_kernel(const float* __restrict__ conv_w, const float* __restrict__ conv_b) {
    int b = blockIdx.z, lt = blockIdx.y, ct = blockIdx.x;
    int c0 = ct * 32;
    int l0 = lt * 32;
    __shared__ float s[35][33];
    for (int i = threadIdx.x; i < 35*32; i += 256) {
        int li = i >> 5, ci = i & 31;
        int l = l0 - 3 + li;
        s[li][ci] = (l >= 0) ? g_xz[((size_t)b*4096 + l)*512 + c0 + ci] : 0.f;
    }
    __syncthreads();
    int li = threadIdx.x & 31;
    int cw0 = threadIdx.x >> 5;
    if (c0 < 256) {
        for (int ci = cw0; ci < 32; ci += 8) {
            int c = c0 + ci;
            float w0 = conv_w[c*4+0], w1 = conv_w[c*4+1], w2 = conv_w[c*4+2], w3 = conv_w[c*4+3];
            float acc = conv_b[c];
            acc = fmaf(w0, s[li][ci], acc);
            acc = fmaf(w1, s[li+1][ci], acc);
            acc = fmaf(w2, s[li+2][ci], acc);
            acc = fmaf(w3, s[li+3][ci], acc);
            g_x[((size_t)(b*256 + c))*4096 + l0 + li] = silu_f(acc);
        }
    } else {
        for (int ci = cw0; ci < 32; ci += 8) {
            int zc = c0 + ci - 256;
            g_z[((size_t)(b*256 + zc))*4096 + l0 + li] = silu_f(s[li+3][ci]);
        }
    }
}

// ---------------- K3: dbl = x @ x_w^T (N=40) -> B,C + fused dt projection ----------------
__global__ void gemm2_kernel(const float* __restrict__ x_w, const float* __restrict__ dt_w,
                             const float* __restrict__ dt_b) {
    const int b = blockIdx.y;
    const int l0 = blockIdx.x * 64;
    __shared__ float xs[32][66];
    __shared__ float ws[40][33];
    __shared__ float sdtr[64][9];
    __shared__ float sdw[256*8];
    __shared__ float sdb[256];
    const int tid = threadIdx.x;
    const int tcol = tid & 31;
    const int trow = tid >> 5;
    float acc[2][5];
    #pragma unroll
    for (int i = 0; i < 2; i++)
        #pragma unroll
        for (int j = 0; j < 5; j++) acc[i][j] = 0.f;

    for (int i = tid; i < 2048; i += 256) sdw[i] = dt_w[i];
    if (tid < 256) sdb[tid] = dt_b[tid];

    for (int k0 = 0; k0 < 256; k0 += 32) {
        #pragma unroll
        for (int i = tid; i < 2048; i += 256) {
            int kk = i >> 6, lx = i & 63;
            xs[kk][lx] = g_x[((size_t)(b*256 + k0 + kk))*4096 + l0 + lx];
        }
        #pragma unroll
        for (int i = tid; i < 1280; i += 256) {
            int j = i >> 5, kk = i & 31;
            ws[j][kk] = x_w[j*256 + k0 + kk];
        }
        __syncthreads();
        #pragma unroll
        for (int kk = 0; kk < 32; kk++) {
            float2 a = *(const float2*)&xs[kk][tcol*2];
            float w[5];
            #pragma unroll
            for (int jj = 0; jj < 5; jj++) w[jj] = ws[trow*5 + jj][kk];
            #pragma unroll
            for (int jj = 0; jj < 5; jj++) {
                acc[0][jj] = fmaf(a.x, w[jj], acc[0][jj]);
                acc[1][jj] = fmaf(a.y, w[jj], acc[1][jj]);
            }
        }
        __syncthreads();
    }
    #pragma unroll
    for (int i = 0; i < 2; i++) {
        int lx = tcol*2 + i;
        int l = l0 + lx;
        #pragma unroll
        for (int jj = 0; jj < 5; jj++) {
            int j = trow*5 + jj;
            float v = acc[i][jj];
            if (j < 8)       sdtr[lx][j] = v;
            else if (j < 24) g_Bm[((size_t)b*4096 + l)*16 + (j - 8)]  = v;
            else             g_Cm[((size_t)b*4096 + l)*16 + (j - 24)] = v;
        }
    }
    __syncthreads();
    int lx = tid & 63;
    int dg = tid >> 6;
    float r0 = sdtr[lx][0], r1 = sdtr[lx][1], r2 = sdtr[lx][2], r3 = sdtr[lx][3];
    float r4 = sdtr[lx][4], r5 = sdtr[lx][5], r6 = sdtr[lx][6], r7 = sdtr[lx][7];
    #pragma unroll 4
    for (int dd = 0; dd < 64; dd++) {
        int d = dg*64 + dd;
        const float* w = &sdw[d*8];
        float a = sdb[d];
        a = fmaf(r0, w[0], a); a = fmaf(r1, w[1], a);
        a = fmaf(r2, w[2], a); a = fmaf(r3, w[3], a);
        a = fmaf(r4, w[4], a); a = fmaf(r5, w[5], a);
        a = fmaf(r6, w[6], a); a = fmaf(r7, w[7], a);
        g_dt[((size_t)(b*256 + d))*4096 + l0 + lx] = softplus_f(a);
    }
}

// ---------------- K5a: scan pass A ----------------
__global__ void scanA_kernel(const float* __restrict__ A_log) {
    int tid = threadIdx.x;
    int n = tid & 15;
    int task = blockIdx.x * 16 + (tid >> 4);
    int chain = task >> 4;
    int s = task & 15;
    int b = chain >> 8, d = chain & 255;
    int l0 = s * SEGL;
    const float* dtp = g_dt + (size_t)chain*4096 + l0;
    const float* xp  = g_x  + (size_t)chain*4096 + l0;
    const float* Bp  = g_Bm + ((size_t)b*4096 + l0)*16 + n;
    float An = -__expf(A_log[d*16 + n]);
    float h = 0.f, P = 1.f;
    for (int l = 0; l < SEGL; l += 4) {
        float4 dt4 = *(const float4*)(dtp + l);
        float4 x4  = *(const float4*)(xp  + l);
        float dta[4] = {dt4.x, dt4.y, dt4.z, dt4.w};
        float xa [4] = {x4.x,  x4.y,  x4.z,  x4.w};
        #pragma unroll
        for (int i = 0; i < 4; i++) {
            float dt = dta[i];
            float Bv = Bp[(l + i)*16];
            float dA = __expf(dt * An);
            P *= dA;
            h = fmaf(dA, h, dt * xa[i] * Bv);
        }
    }
    g_segH[task*16 + n] = h;
    g_segP[task*16 + n] = P;
}

// ---------------- K5b: combine; zero cmean ----------------
__global__ void scanC_kernel() {
    int t = blockIdx.x * 256 + threadIdx.x;
    if (t < 128) g_cmean[t] = 0.f;
    int chain = t >> 4, n = t & 15;
    float h = 0.f;
    #pragma unroll
    for (int s = 0; s < NSEG; s++) {
        int idx = (chain*16 + s)*16 + n;
        g_h0[idx] = h;
        h = g_segH[idx] + g_segP[idx]*h;
    }
}

// ---------------- K5c: scan pass B ----------------
__global__ void scanB_kernel(const float* __restrict__ A_log, const float* __restrict__ Dp) {
    int tid = threadIdx.x;
    int n = tid & 15;
    int task = blockIdx.x * 16 + (tid >> 4);
    int chain = task >> 4;
    int s = task & 15;
    int b = chain >> 8, d = chain & 255;
    int l0 = s * SEGL;
    const float* dtp = g_dt + (size_t)chain*4096 + l0;
    const float* xp  = g_x  + (size_t)chain*4096 + l0;
    const float* zp  = g_z  + (size_t)chain*4096 + l0;   // pre-gated silu(z)
    const float* Bp  = g_Bm + ((size_t)b*4096 + l0)*16 + n;
    const float* Cp  = g_Cm + ((size_t)b*4096 + l0)*16 + n;
    float* yout = g_y + (size_t)chain*4096 + l0;
    float An = -__expf(A_log[d*16 + n]);
    float Dd = Dp[d];
    float h = g_h0[task*16 + n];
    for (int l = 0; l < SEGL; l += 4) {
        float4 dt4 = *(const float4*)(dtp + l);
        float4 x4  = *(const float4*)(xp  + l);
        float4 z4  = *(const float4*)(zp  + l);
        float dta[4] = {dt4.x, dt4.y, dt4.z, dt4.w};
        float xa [4] = {x4.x,  x4.y,  x4.z,  x4.w};
        float ga [4] = {z4.x,  z4.y,  z4.z,  z4.w};
        float ov[4];
        #pragma unroll
        for (int i = 0; i < 4; i++) {
            float dt = dta[i];
            float Bv = Bp[(l + i)*16];
            float Cv = Cp[(l + i)*16];
            float dA = __expf(dt * An);
            h = fmaf(dA, h, dt * xa[i] * Bv);
            float y = h * Cv;
            y += __shfl_xor_sync(0xFFFFFFFFu, y, 8);
            y += __shfl_xor_sync(0xFFFFFFFFu, y, 4);
            y += __shfl_xor_sync(0xFFFFFFFFu, y, 2);
            y += __shfl_xor_sync(0xFFFFFFFFu, y, 1);
            ov[i] = fmaf(xa[i], Dd, y) * ga[i];
        }
        if (n == 0) {
            *(float4*)(yout + l) = make_float4(ov[0], ov[1], ov[2], ov[3]);
        }
    }
}

// ---------------- K7: res + cmean ----------------
__global__ void gemm3t_kernel(const float* __restrict__ fo2, const float* __restrict__ out_w) {
    int b = blockIdx.x >> 5, lt = blockIdx.x & 31;
    int l0 = lt * 128;
    __shared__ float xs[16][128];
    __shared__ float ws[32][17];
    int tid = threadIdx.x;
    int ll = tid & 127, jg = tid >> 7;
    int lane = tid & 31;
    float acc[16];
    #pragma unroll
    for (int j = 0; j < 16; j++) acc[j] = 0.f;

    for (int k0 = 0; k0 < 256; k0 += 16) {
        for (int i = tid; i < 16*128; i += 256) {
            int di = i >> 7, lix = i & 127;
            xs[di][lix] = g_y[((size_t)(b*256 + k0 + di))*4096 + l0 + lix];
        }
        for (int i = tid; i < 32*16; i += 256) {
            int j = i / 16, kk = i % 16;
            int col = k0 + kk;
            ws[j][kk] = out_w[j*256 + col] + out_w[(32 + j)*256 + col]
                      + out_w[(64 + j)*256 + col] + out_w[(96 + j)*256 + col];
        }
        __syncthreads();
        #pragma unroll
        for (int di = 0; di < 16; di++) {
            float a = xs[di][ll];
            #pragma unroll
            for (int jj = 0; jj < 16; jj++)
                acc[jj] = fmaf(a, ws[jg*16 + jj][di], acc[jj]);
        }
        __syncthreads();
    }
    int l = l0 + ll;
    #pragma unroll
    for (int jj = 0; jj < 16; jj++) {
        int c = jg*16 + jj;
        size_t idx = ((size_t)(b*32 + c))*4096 + l;
        float r = acc[jj] * fo2[idx];
        g_residual[idx] = r;
        float s = r;
        s += __shfl_xor_sync(0xFFFFFFFFu, s, 16);
        s += __shfl_xor_sync(0xFFFFFFFFu, s, 8);
        s += __shfl_xor_sync(0xFFFFFFFFu, s, 4);
        s += __shfl_xor_sync(0xFFFFFFFFu, s, 2);
        s += __shfl_xor_sync(0xFFFFFFFFu, s, 1);
        if (lane == 0) atomicAdd(&g_cmean[b*32 + c], s);
    }
}

// ---------------- K9: tiny mamba2 ----------------
__global__ void mamba2_kernel(const float* __restrict__ in_w, const float* __restrict__ conv_w,
                              const float* __restrict__ conv_b, const float* __restrict__ x_w,
                              const float* __restrict__ dt_w, const float* __restrict__ dt_b,
                              const float* __restrict__ A_log, const float* __restrict__ Dp,
                              const float* __restrict__ out_w) {
    __shared__ float sxp[4][32][4];
    __shared__ float sx [4][32][4];
    __shared__ float sz [4][32][4];
    __shared__ float sdt[4][32][4];
    __shared__ float sB [4][32][16];
    __shared__ float sC [4][32][16];
    __shared__ float sy [4][32][4];
    int tid = threadIdx.x;
    int b = tid >> 5, l = tid & 31;
    float m0 = g_cmean[b*32 + l] * (1.f/4096.f);
    float m1 = g_cmean[b*32 + 31 - l] * (1.f/4096.f);
    #pragma unroll
    for (int j = 0; j < 4; j++) {
        sxp[b][l][j] = m0*in_w[j*2]       + m1*in_w[j*2 + 1];
        sz [b][l][j] = m0*in_w[(j+4)*2]   + m1*in_w[(j+4)*2 + 1];
    }
    __syncthreads();
    #pragma unroll
    for (int c = 0; c < 4; c++) {
        float acc = conv_b[c];
        #pragma unroll
        for (int t = 0; t < 4; t++) {
            int ls = l - 3 + t;
            float v = (ls >= 0) ? sxp[b][ls][c] : 0.f;
            acc = fmaf(conv_w[c*4 + t], v, acc);
        }
        sx[b][l][c] = acc / (1.f + expf(-acc));
    }
    __syncthreads();
    {
        float xv[4] = {sx[b][l][0], sx[b][l][1], sx[b][l][2], sx[b][l][3]};
        float dtr = 0.f;
        #pragma unroll
        for (int c = 0; c < 4; c++) dtr = fmaf(xv[c], x_w[c], dtr);
        #pragma unroll
        for (int n = 0; n < 16; n++) {
            float bb = 0.f, cc = 0.f;
            #pragma unroll
            for (int c = 0; c < 4; c++) {
                bb = fmaf(xv[c], x_w[(1 + n)*4 + c], bb);
                cc = fmaf(xv[c], x_w[(17 + n)*4 + c], cc);
            }
            sB[b][l][n] = bb;
            sC[b][l][n] = cc;
        }
        #pragma unroll
        for (int dd = 0; dd < 4; dd++) {
            float a = fmaf(dtr, dt_w[dd], dt_b[dd]);
            sdt[b][l][dd] = (a > 20.f) ? a : log1pf(expf(a));
        }
    }
    __syncthreads();
    {
        int lane = tid & 31, wb = tid >> 5;
        int grp = lane >> 4, n = lane & 15;
        int d0 = grp, d1 = grp + 2;
        float A0 = -expf(A_log[d0*16 + n]);
        float A1 = -expf(A_log[d1*16 + n]);
        float h0 = 0.f, h1 = 0.f;
        for (int t = 0; t < 32; t++) {
            float Bv = sB[wb][t][n], Cv = sC[wb][t][n];
            float dt0 = sdt[wb][t][d0], x0 = sx[wb][t][d0];
            float dt1 = sdt[wb][t][d1], x1 = sx[wb][t][d1];
            h0 = fmaf(__expf(dt0*A0), h0, dt0*x0*Bv);
            h1 = fmaf(__expf(dt1*A1), h1, dt1*x1*Bv);
            float y0 = h0*Cv, y1 = h1*Cv;
            y0 += __shfl_xor_sync(0xFFFFFFFFu, y0, 8);
            y0 += __shfl_xor_sync(0xFFFFFFFFu, y0, 4);
            y0 += __shfl_xor_sync(0xFFFFFFFFu, y0, 2);
            y0 += __shfl_xor_sync(0xFFFFFFFFu, y0, 1);
            y1 += __shfl_xor_sync(0xFFFFFFFFu, y1, 8);
            y1 += __shfl_xor_sync(0xFFFFFFFFu, y1, 4);
            y1 += __shfl_xor_sync(0xFFFFFFFFu, y1, 2);
            y1 += __shfl_xor_sync(0xFFFFFFFFu, y1, 1);
            if (n == 0) { sy[wb][t][d0] = y0; sy[wb][t][d1] = y1; }
        }
    }
    __syncthreads();
    {
        float scale = 0.f;
        #pragma unroll
        for (int dd = 0; dd < 4; dd++) {
            float yv = fmaf(sx[b][l][dd], Dp[dd], sy[b][l][dd]);
            float zz = sz[b][l][dd];
            yv *= zz / (1.f + expf(-zz));
            scale = fmaf(yv, out_w[dd] + out_w[4 + dd], scale);
        }
        g_scale[b*32 + l] = scale;
    }
}

// ---------------- K10: out = residual * (scale + 1) ----------------
__global__ void final_kernel(float* __restrict__ out) {
    int idx = blockIdx.x * 256 + threadIdx.x;
    out[idx] = g_residual[idx] * (g_scale[idx >> 12] + 1.f);
}

// ---------------- launch ----------------
extern "C" void kernel_launch(void* const* d_in, const int* in_sizes, int n_in,
                              void* d_out, int out_size) {
    const float* fo1      = (const float*)d_in[0];
    const float* fo2      = (const float*)d_in[1];
    const float* m1_in_w  = (const float*)d_in[2];
    const float* m1_conv_w= (const float*)d_in[3];
    const float* m1_conv_b= (const float*)d_in[4];
    const float* m1_x_w   = (const float*)d_in[5];
    const float* m1_dt_w  = (const float*)d_in[6];
    const float* m1_dt_b  = (const float*)d_in[7];
    const float* m1_A_log = (const float*)d_in[8];
    const float* m1_D     = (const float*)d_in[9];
    const float* m1_out_w = (const float*)d_in[10];
    const float* m2_in_w  = (const float*)d_in[11];
    const float* m2_conv_w= (const float*)d_in[12];
    const float* m2_conv_b= (const float*)d_in[13];
    const float* m2_x_w   = (const float*)d_in[14];
    const float* m2_dt_w  = (const float*)d_in[15];
    const float* m2_dt_b  = (const float*)d_in[16];
    const float* m2_A_log = (const float*)d_in[17];
    const float* m2_D     = (const float*)d_in[18];
    const float* m2_out_w = (const float*)d_in[19];
    float* out = (float*)d_out;

    gemm1_kernel<<<dim3(4, 128), 256>>>(fo1, m1_in_w);
    conv_transpose_kernel<<<dim3(16, 128, 4), 256>>>(m1_conv_w, m1_conv_b);
    gemm2_kernel<<<dim3(64, 4), 256>>>(m1_x_w, m1_dt_w, m1_dt_b);
    scanA_kernel<<<1024, 256>>>(m1_A_log);
    scanC_kernel<<<64, 256>>>();
    scanB_kernel<<<1024, 256>>>(m1_A_log, m1_D);
    gemm3t_kernel<<<128, 256>>>(fo2, m1_out_w);
    mamba2_kernel<<<1, 128>>>(m2_in_w, m2_conv_w, m2_conv_b, m2_x_w, m2_dt_w,
                              m2_dt_b, m2_A_log, m2_D, m2_out_w);
    final_kernel<<<2048, 256>>>(out);
}

// round 13
// speedup vs baseline: 1.4441x; 1.0327x over previous
#include <cuda_runtime.h>
#include <cuda_bf16.h>
#include <math.h>
#include <cstdint>

#define Bsz 4
#define Lseq 4096
#define DIN 256
#define DST 16
#define DTR 8
#define NSEG 16
#define SEGL 256   // Lseq / NSEG

// ---------------- scratch ----------------
__device__ __align__(16) float g_xz [Bsz*Lseq*512];      // (b,l,512)
__device__ __align__(16) float g_x  [Bsz*DIN*Lseq];      // post-conv silu, (b,d,l)
__device__ __align__(16) float g_z  [Bsz*DIN*Lseq];      // silu(z) gate, (b,d,l)
__device__ __align__(16) float g_dt [Bsz*DIN*Lseq];      // (b,d,l)
__device__ __align__(16) float g_Bm [Bsz*Lseq*DST];      // (b,l,16)
__device__ __align__(16) float g_Cm [Bsz*Lseq*DST];      // (b,l,16)
__device__ __align__(16) float g_y  [Bsz*DIN*Lseq];      // (b,d,l)
__device__ __align__(16) float g_residual[Bsz*32*Lseq];  // (b,c,h,w)
__device__ __align__(16) float g_segH[Bsz*DIN*NSEG*DST];
__device__ __align__(16) float g_segP[Bsz*DIN*NSEG*DST];
__device__ __align__(16) float g_h0  [Bsz*DIN*NSEG*DST];
__device__ float g_cmean[Bsz*32];
__device__ float g_scale[Bsz*32];

__device__ __forceinline__ float silu_f(float v) { return v / (1.f + __expf(-v)); }
__device__ __forceinline__ float softplus_f(float v) { return (v > 20.f) ? v : log1pf(__expf(v)); }

// ---------------- K1: xz = fop @ in_w^T via mma.sync bf16-split (HMMA) ----------------
// Block 256 thr = 8 warps (4m x 2n).  Tile: 128m x 64n, K in 4 chunks of 32.
// D = Ahi*Bhi + Ahi*Blo + Alo*Bhi, fp32 accum.
__global__ void __launch_bounds__(256) gemm1_mma_kernel(const float* __restrict__ fo1,
                                                        const float* __restrict__ in_w) {
    __shared__ __nv_bfloat16 Ahi[128][36];
    __shared__ __nv_bfloat16 Alo[128][36];
    __shared__ __nv_bfloat16 Bhi[64][36];
    __shared__ __nv_bfloat16 Blo[64][36];
    const int tid = threadIdx.x;
    const int wid = tid >> 5, lane = tid & 31;
    const int bm = blockIdx.y * 128, bn = blockIdx.x * 64;
    const int b = bm >> 12;
    const int wrow = (wid >> 1) * 32;       // warp m-offset
    const int wcol = (wid & 1) * 32;        // warp n-offset
    const int r = lane >> 2, q = lane & 3;

    float acc[2][4][4];
    #pragma unroll
    for (int mt = 0; mt < 2; mt++)
        #pragma unroll
        for (int nt = 0; nt < 4; nt++)
            #pragma unroll
            for (int i = 0; i < 4; i++) acc[mt][nt][i] = 0.f;

    for (int k0 = 0; k0 < 128; k0 += 32) {
        // stage A (gathered from fo1) hi/lo: 128m x 32k
        #pragma unroll
        for (int it = 0; it < 16; it++) {
            int e = tid + it*256;
            int m = e & 127, kk = e >> 7;          // kk 0..31
            int j = k0 + kk;                        // channel
            int g = j >> 5, c = j & 31;
            int l = (bm + m) & 4095;
            int l2 = (g & 1) ? 4095 - l : l;
            int pos = (g < 2) ? l2 : (((l2 & 63) << 6) | (l2 >> 6));
            float v = fo1[((size_t)(b*32 + c))*4096 + pos];
            __nv_bfloat16 h = __float2bfloat16(v);
            Ahi[m][kk] = h;
            Alo[m][kk] = __float2bfloat16(v - __bfloat162float(h));
        }
        // stage B hi/lo: 64n x 32k
        #pragma unroll
        for (int it = 0; it < 8; it++) {
            int e = tid + it*256;
            int n = e & 63, kk = e >> 6;
            float v = in_w[(size_t)(bn + n)*128 + k0 + kk];
            __nv_bfloat16 h = __float2bfloat16(v);
            Bhi[n][kk] = h;
            Blo[n][kk] = __float2bfloat16(v - __bfloat162float(h));
        }
        __syncthreads();

        #pragma unroll
        for (int kc = 0; kc < 2; kc++) {
            const int kb = kc*16 + q*2;
            uint32_t ah[2][4], al[2][4], bh[4][2], bl[4][2];
            #pragma unroll
            for (int mt = 0; mt < 2; mt++) {
                int m0 = wrow + mt*16;
                ah[mt][0] = *(const uint32_t*)&Ahi[m0 + r][kb];
                ah[mt][1] = *(const uint32_t*)&Ahi[m0 + r + 8][kb];
                ah[mt][2] = *(const uint32_t*)&Ahi[m0 + r][kb + 8];
                ah[mt][3] = *(const uint32_t*)&Ahi[m0 + r + 8][kb + 8];
                al[mt][0] = *(const uint32_t*)&Alo[m0 + r][kb];
                al[mt][1] = *(const uint32_t*)&Alo[m0 + r + 8][kb];
                al[mt][2] = *(const uint32_t*)&Alo[m0 + r][kb + 8];
                al[mt][3] = *(const uint32_t*)&Alo[m0 + r + 8][kb + 8];
            }
            #pragma unroll
            for (int nt = 0; nt < 4; nt++) {
                int n0 = wcol + nt*8;
                bh[nt][0] = *(const uint32_t*)&Bhi[n0 + r][kb];
                bh[nt][1] = *(const uint32_t*)&Bhi[n0 + r][kb + 8];
                bl[nt][0] = *(const uint32_t*)&Blo[n0 + r][kb];
                bl[nt][1] = *(const uint32_t*)&Blo[n0 + r][kb + 8];
            }
            #pragma unroll
            for (int mt = 0; mt < 2; mt++)
                #pragma unroll
                for (int nt = 0; nt < 4; nt++) {
                    float* c = acc[mt][nt];
                    asm volatile(
                        "mma.sync.aligned.m16n8k16.row.col.f32.bf16.bf16.f32 "
                        "{%0,%1,%2,%3}, {%4,%5,%6,%7}, {%8,%9}, {%0,%1,%2,%3};"
                        : "+f"(c[0]), "+f"(c[1]), "+f"(c[2]), "+f"(c[3])
                        : "r"(ah[mt][0]), "r"(ah[mt][1]), "r"(ah[mt][2]), "r"(ah[mt][3]),
                          "r"(bh[nt][0]), "r"(bh[nt][1]));
                    asm volatile(
                        "mma.sync.aligned.m16n8k16.row.col.f32.bf16.bf16.f32 "
                        "{%0,%1,%2,%3}, {%4,%5,%6,%7}, {%8,%9}, {%0,%1,%2,%3};"
                        : "+f"(c[0]), "+f"(c[1]), "+f"(c[2]), "+f"(c[3])
                        : "r"(ah[mt][0]), "r"(ah[mt][1]), "r"(ah[mt][2]), "r"(ah[mt][3]),
                          "r"(bl[nt][0]), "r"(bl[nt][1]));
                    asm volatile(
                        "mma.sync.aligned.m16n8k16.row.col.f32.bf16.bf16.f32 "
                        "{%0,%1,%2,%3}, {%4,%5,%6,%7}, {%8,%9}, {%0,%1,%2,%3};"
                        : "+f"(c[0]), "+f"(c[1]), "+f"(c[2]), "+f"(c[3])
                        : "r"(al[mt][0]), "r"(al[mt][1]), "r"(al[mt][2]), "r"(al[mt][3]),
                          "r"(bh[nt][0]), "r"(bh[nt][1]));
                }
        }
        __syncthreads();
    }

    // epilogue: c0,c1 at (row, col..col+1), c2,c3 at (row+8, col..col+1)
    #pragma unroll
    for (int mt = 0; mt < 2; mt++) {
        #pragma unroll
        for (int nt = 0; nt < 4; nt++) {
            int row = bm + wrow + mt*16 + r;
            int col = bn + wcol + nt*8 + q*2;
            float* c = acc[mt][nt];
            *(float2*)&g_xz[(size_t)row*512 + col]       = make_float2(c[0], c[1]);
            *(float2*)&g_xz[(size_t)(row + 8)*512 + col] = make_float2(c[2], c[3]);
        }
    }
}

// ---------------- K2: causal depthwise conv(4)+bias+silu; z stored as silu(z) gate ----------------
__global__ void conv_transpose_kernel(const float* __restrict__ conv_w, const float* __restrict__ conv_b) {
    int b = blockIdx.z, lt = blockIdx.y, ct = blockIdx.x;
    int c0 = ct * 32;
    int l0 = lt * 32;
    __shared__ float s[35][33];
    for (int i = threadIdx.x; i < 35*32; i += 256) {
        int li = i >> 5, ci = i & 31;
        int l = l0 - 3 + li;
        s[li][ci] = (l >= 0) ? g_xz[((size_t)b*4096 + l)*512 + c0 + ci] : 0.f;
    }
    __syncthreads();
    int li = threadIdx.x & 31;
    int cw0 = threadIdx.x >> 5;
    if (c0 < 256) {
        for (int ci = cw0; ci < 32; ci += 8) {
            int c = c0 + ci;
            float w0 = conv_w[c*4+0], w1 = conv_w[c*4+1], w2 = conv_w[c*4+2], w3 = conv_w[c*4+3];
            float acc = conv_b[c];
            acc = fmaf(w0, s[li][ci], acc);
            acc = fmaf(w1, s[li+1][ci], acc);
            acc = fmaf(w2, s[li+2][ci], acc);
            acc = fmaf(w3, s[li+3][ci], acc);
            g_x[((size_t)(b*256 + c))*4096 + l0 + li] = silu_f(acc);
        }
    } else {
        for (int ci = cw0; ci < 32; ci += 8) {
            int zc = c0 + ci - 256;
            g_z[((size_t)(b*256 + zc))*4096 + l0 + li] = silu_f(s[li+3][ci]);
        }
    }
}

// ---------------- K3: dbl = x @ x_w^T (N=40) -> B,C + fused dt projection ----------------
__global__ void gemm2_kernel(const float* __restrict__ x_w, const float* __restrict__ dt_w,
                             const float* __restrict__ dt_b) {
    const int b = blockIdx.y;
    const int l0 = blockIdx.x * 64;
    __shared__ float xs[32][66];
    __shared__ float ws[40][33];
    __shared__ float sdtr[64][9];
    __shared__ float sdw[256*8];
    __shared__ float sdb[256];
    const int tid = threadIdx.x;
    const int tcol = tid & 31;
    const int trow = tid >> 5;
    float acc[2][5];
    #pragma unroll
    for (int i = 0; i < 2; i++)
        #pragma unroll
        for (int j = 0; j < 5; j++) acc[i][j] = 0.f;

    for (int i = tid; i < 2048; i += 256) sdw[i] = dt_w[i];
    if (tid < 256) sdb[tid] = dt_b[tid];

    for (int k0 = 0; k0 < 256; k0 += 32) {
        #pragma unroll
        for (int i = tid; i < 2048; i += 256) {
            int kk = i >> 6, lx = i & 63;
            xs[kk][lx] = g_x[((size_t)(b*256 + k0 + kk))*4096 + l0 + lx];
        }
        #pragma unroll
        for (int i = tid; i < 1280; i += 256) {
            int j = i >> 5, kk = i & 31;
            ws[j][kk] = x_w[j*256 + k0 + kk];
        }
        __syncthreads();
        #pragma unroll
        for (int kk = 0; kk < 32; kk++) {
            float2 a = *(const float2*)&xs[kk][tcol*2];
            float w[5];
            #pragma unroll
            for (int jj = 0; jj < 5; jj++) w[jj] = ws[trow*5 + jj][kk];
            #pragma unroll
            for (int jj = 0; jj < 5; jj++) {
                acc[0][jj] = fmaf(a.x, w[jj], acc[0][jj]);
                acc[1][jj] = fmaf(a.y, w[jj], acc[1][jj]);
            }
        }
        __syncthreads();
    }
    #pragma unroll
    for (int i = 0; i < 2; i++) {
        int lx = tcol*2 + i;
        int l = l0 + lx;
        #pragma unroll
        for (int jj = 0; jj < 5; jj++) {
            int j = trow*5 + jj;
            float v = acc[i][jj];
            if (j < 8)       sdtr[lx][j] = v;
            else if (j < 24) g_Bm[((size_t)b*4096 + l)*16 + (j - 8)]  = v;
            else             g_Cm[((size_t)b*4096 + l)*16 + (j - 24)] = v;
        }
    }
    __syncthreads();
    int lx = tid & 63;
    int dg = tid >> 6;
    float r0 = sdtr[lx][0], r1 = sdtr[lx][1], r2 = sdtr[lx][2], r3 = sdtr[lx][3];
    float r4 = sdtr[lx][4], r5 = sdtr[lx][5], r6 = sdtr[lx][6], r7 = sdtr[lx][7];
    #pragma unroll 4
    for (int dd = 0; dd < 64; dd++) {
        int d = dg*64 + dd;
        const float* w = &sdw[d*8];
        float a = sdb[d];
        a = fmaf(r0, w[0], a); a = fmaf(r1, w[1], a);
        a = fmaf(r2, w[2], a); a = fmaf(r3, w[3], a);
        a = fmaf(r4, w[4], a); a = fmaf(r5, w[5], a);
        a = fmaf(r6, w[6], a); a = fmaf(r7, w[7], a);
        g_dt[((size_t)(b*256 + d))*4096 + l0 + lx] = softplus_f(a);
    }
}

// ---------------- K5a: scan pass A ----------------
__global__ void scanA_kernel(const float* __restrict__ A_log) {
    int tid = threadIdx.x;
    int n = tid & 15;
    int task = blockIdx.x * 16 + (tid >> 4);
    int chain = task >> 4;
    int s = task & 15;
    int b = chain >> 8, d = chain & 255;
    int l0 = s * SEGL;
    const float* dtp = g_dt + (size_t)chain*4096 + l0;
    const float* xp  = g_x  + (size_t)chain*4096 + l0;
    const float* Bp  = g_Bm + ((size_t)b*4096 + l0)*16 + n;
    float An = -__expf(A_log[d*16 + n]);
    float h = 0.f, P = 1.f;
    for (int l = 0; l < SEGL; l += 4) {
        float4 dt4 = *(const float4*)(dtp + l);
        float4 x4  = *(const float4*)(xp  + l);
        float dta[4] = {dt4.x, dt4.y, dt4.z, dt4.w};
        float xa [4] = {x4.x,  x4.y,  x4.z,  x4.w};
        #pragma unroll
        for (int i = 0; i < 4; i++) {
            float dt = dta[i];
            float Bv = Bp[(l + i)*16];
            float dA = __expf(dt * An);
            P *= dA;
            h = fmaf(dA, h, dt * xa[i] * Bv);
        }
    }
    g_segH[task*16 + n] = h;
    g_segP[task*16 + n] = P;
}

// ---------------- K5b: combine; zero cmean ----------------
__global__ void scanC_kernel() {
    int t = blockIdx.x * 256 + threadIdx.x;
    if (t < 128) g_cmean[t] = 0.f;
    int chain = t >> 4, n = t & 15;
    float h = 0.f;
    #pragma unroll
    for (int s = 0; s < NSEG; s++) {
        int idx = (chain*16 + s)*16 + n;
        g_h0[idx] = h;
        h = g_segH[idx] + g_segP[idx]*h;
    }
}

// ---------------- K5c: scan pass B ----------------
__global__ void scanB_kernel(const float* __restrict__ A_log, const float* __restrict__ Dp) {
    int tid = threadIdx.x;
    int n = tid & 15;
    int task = blockIdx.x * 16 + (tid >> 4);
    int chain = task >> 4;
    int s = task & 15;
    int b = chain >> 8, d = chain & 255;
    int l0 = s * SEGL;
    const float* dtp = g_dt + (size_t)chain*4096 + l0;
    const float* xp  = g_x  + (size_t)chain*4096 + l0;
    const float* zp  = g_z  + (size_t)chain*4096 + l0;   // pre-gated silu(z)
    const float* Bp  = g_Bm + ((size_t)b*4096 + l0)*16 + n;
    const float* Cp  = g_Cm + ((size_t)b*4096 + l0)*16 + n;
    float* yout = g_y + (size_t)chain*4096 + l0;
    float An = -__expf(A_log[d*16 + n]);
    float Dd = Dp[d];
    float h = g_h0[task*16 + n];
    for (int l = 0; l < SEGL; l += 4) {
        float4 dt4 = *(const float4*)(dtp + l);
        float4 x4  = *(const float4*)(xp  + l);
        float4 z4  = *(const float4*)(zp  + l);
        float dta[4] = {dt4.x, dt4.y, dt4.z, dt4.w};
        float xa [4] = {x4.x,  x4.y,  x4.z,  x4.w};
        float ga [4] = {z4.x,  z4.y,  z4.z,  z4.w};
        float ov[4];
        #pragma unroll
        for (int i = 0; i < 4; i++) {
            float dt = dta[i];
            float Bv = Bp[(l + i)*16];
            float Cv = Cp[(l + i)*16];
            float dA = __expf(dt * An);
            h = fmaf(dA, h, dt * xa[i] * Bv);
            float y = h * Cv;
            y += __shfl_xor_sync(0xFFFFFFFFu, y, 8);
            y += __shfl_xor_sync(0xFFFFFFFFu, y, 4);
            y += __shfl_xor_sync(0xFFFFFFFFu, y, 2);
            y += __shfl_xor_sync(0xFFFFFFFFu, y, 1);
            ov[i] = fmaf(xa[i], Dd, y) * ga[i];
        }
        if (n == 0) {
            *(float4*)(yout + l) = make_float4(ov[0], ov[1], ov[2], ov[3]);
        }
    }
}

// ---------------- K7: res + cmean ----------------
__global__ void gemm3t_kernel(const float* __restrict__ fo2, const float* __restrict__ out_w) {
    int b = blockIdx.x >> 5, lt = blockIdx.x & 31;
    int l0 = lt * 128;
    __shared__ float xs[16][128];
    __shared__ float ws[32][17];
    int tid = threadIdx.x;
    int ll = tid & 127, jg = tid >> 7;
    int lane = tid & 31;
    float acc[16];
    #pragma unroll
    for (int j = 0; j < 16; j++) acc[j] = 0.f;

    for (int k0 = 0; k0 < 256; k0 += 16) {
        for (int i = tid; i < 16*128; i += 256) {
            int di = i >> 7, lix = i & 127;
            xs[di][lix] = g_y[((size_t)(b*256 + k0 + di))*4096 + l0 + lix];
        }
        for (int i = tid; i < 32*16; i += 256) {
            int j = i / 16, kk = i % 16;
            int col = k0 + kk;
            ws[j][kk] = out_w[j*256 + col] + out_w[(32 + j)*256 + col]
                      + out_w[(64 + j)*256 + col] + out_w[(96 + j)*256 + col];
        }
        __syncthreads();
        #pragma unroll
        for (int di = 0; di < 16; di++) {
            float a = xs[di][ll];
            #pragma unroll
            for (int jj = 0; jj < 16; jj++)
                acc[jj] = fmaf(a, ws[jg*16 + jj][di], acc[jj]);
        }
        __syncthreads();
    }
    int l = l0 + ll;
    #pragma unroll
    for (int jj = 0; jj < 16; jj++) {
        int c = jg*16 + jj;
        size_t idx = ((size_t)(b*32 + c))*4096 + l;
        float r = acc[jj] * fo2[idx];
        g_residual[idx] = r;
        float s = r;
        s += __shfl_xor_sync(0xFFFFFFFFu, s, 16);
        s += __shfl_xor_sync(0xFFFFFFFFu, s, 8);
        s += __shfl_xor_sync(0xFFFFFFFFu, s, 4);
        s += __shfl_xor_sync(0xFFFFFFFFu, s, 2);
        s += __shfl_xor_sync(0xFFFFFFFFu, s, 1);
        if (lane == 0) atomicAdd(&g_cmean[b*32 + c], s);
    }
}

// ---------------- K9: tiny mamba2 ----------------
__global__ void mamba2_kernel(const float* __restrict__ in_w, const float* __restrict__ conv_w,
                              const float* __restrict__ conv_b, const float* __restrict__ x_w,
                              const float* __restrict__ dt_w, const float* __restrict__ dt_b,
                              const float* __restrict__ A_log, const float* __restrict__ Dp,
                              const float* __restrict__ out_w) {
    __shared__ float sxp[4][32][4];
    __shared__ float sx [4][32][4];
    __shared__ float sz [4][32][4];
    __shared__ float sdt[4][32][4];
    __shared__ float sB [4][32][16];
    __shared__ float sC [4][32][16];
    __shared__ float sy [4][32][4];
    int tid = threadIdx.x;
    int b = tid >> 5, l = tid & 31;
    float m0 = g_cmean[b*32 + l] * (1.f/4096.f);
    float m1 = g_cmean[b*32 + 31 - l] * (1.f/4096.f);
    #pragma unroll
    for (int j = 0; j < 4; j++) {
        sxp[b][l][j] = m0*in_w[j*2]       + m1*in_w[j*2 + 1];
        sz [b][l][j] = m0*in_w[(j+4)*2]   + m1*in_w[(j+4)*2 + 1];
    }
    __syncthreads();
    #pragma unroll
    for (int c = 0; c < 4; c++) {
        float acc = conv_b[c];
        #pragma unroll
        for (int t = 0; t < 4; t++) {
            int ls = l - 3 + t;
            float v = (ls >= 0) ? sxp[b][ls][c] : 0.f;
            acc = fmaf(conv_w[c*4 + t], v, acc);
        }
        sx[b][l][c] = acc / (1.f + expf(-acc));
    }
    __syncthreads();
    {
        float xv[4] = {sx[b][l][0], sx[b][l][1], sx[b][l][2], sx[b][l][3]};
        float dtr = 0.f;
        #pragma unroll
        for (int c = 0; c < 4; c++) dtr = fmaf(xv[c], x_w[c], dtr);
        #pragma unroll
        for (int n = 0; n < 16; n++) {
            float bb = 0.f, cc = 0.f;
            #pragma unroll
            for (int c = 0; c < 4; c++) {
                bb = fmaf(xv[c], x_w[(1 + n)*4 + c], bb);
                cc = fmaf(xv[c], x_w[(17 + n)*4 + c], cc);
            }
            sB[b][l][n] = bb;
            sC[b][l][n] = cc;
        }
        #pragma unroll
        for (int dd = 0; dd < 4; dd++) {
            float a = fmaf(dtr, dt_w[dd], dt_b[dd]);
            sdt[b][l][dd] = (a > 20.f) ? a : log1pf(expf(a));
        }
    }
    __syncthreads();
    {
        int lane = tid & 31, wb = tid >> 5;
        int grp = lane >> 4, n = lane & 15;
        int d0 = grp, d1 = grp + 2;
        float A0 = -expf(A_log[d0*16 + n]);
        float A1 = -expf(A_log[d1*16 + n]);
        float h0 = 0.f, h1 = 0.f;
        for (int t = 0; t < 32; t++) {
            float Bv = sB[wb][t][n], Cv = sC[wb][t][n];
            float dt0 = sdt[wb][t][d0], x0 = sx[wb][t][d0];
            float dt1 = sdt[wb][t][d1], x1 = sx[wb][t][d1];
            h0 = fmaf(__expf(dt0*A0), h0, dt0*x0*Bv);
            h1 = fmaf(__expf(dt1*A1), h1, dt1*x1*Bv);
            float y0 = h0*Cv, y1 = h1*Cv;
            y0 += __shfl_xor_sync(0xFFFFFFFFu, y0, 8);
            y0 += __shfl_xor_sync(0xFFFFFFFFu, y0, 4);
            y0 += __shfl_xor_sync(0xFFFFFFFFu, y0, 2);
            y0 += __shfl_xor_sync(0xFFFFFFFFu, y0, 1);
            y1 += __shfl_xor_sync(0xFFFFFFFFu, y1, 8);
            y1 += __shfl_xor_sync(0xFFFFFFFFu, y1, 4);
            y1 += __shfl_xor_sync(0xFFFFFFFFu, y1, 2);
            y1 += __shfl_xor_sync(0xFFFFFFFFu, y1, 1);
            if (n == 0) { sy[wb][t][d0] = y0; sy[wb][t][d1] = y1; }
        }
    }
    __syncthreads();
    {
        float scale = 0.f;
        #pragma unroll
        for (int dd = 0; dd < 4; dd++) {
            float yv = fmaf(sx[b][l][dd], Dp[dd], sy[b][l][dd]);
            float zz = sz[b][l][dd];
            yv *= zz / (1.f + expf(-zz));
            scale = fmaf(yv, out_w[dd] + out_w[4 + dd], scale);
        }
        g_scale[b*32 + l] = scale;
    }
}

// ---------------- K10: out = residual * (scale + 1) ----------------
__global__ void final_kernel(float* __restrict__ out) {
    int idx = blockIdx.x * 256 + threadIdx.x;
    out[idx] = g_residual[idx] * (g_scale[idx >> 12] + 1.f);
}

// ---------------- launch ----------------
extern "C" void kernel_launch(void* const* d_in, const int* in_sizes, int n_in,
                              void* d_out, int out_size) {
    const float* fo1      = (const float*)d_in[0];
    const float* fo2      = (const float*)d_in[1];
    const float* m1_in_w  = (const float*)d_in[2];
    const float* m1_conv_w= (const float*)d_in[3];
    const float* m1_conv_b= (const float*)d_in[4];
    const float* m1_x_w   = (const float*)d_in[5];
    const float* m1_dt_w  = (const float*)d_in[6];
    const float* m1_dt_b  = (const float*)d_in[7];
    const float* m1_A_log = (const float*)d_in[8];
    const float* m1_D     = (const float*)d_in[9];
    const float* m1_out_w = (const float*)d_in[10];
    const float* m2_in_w  = (const float*)d_in[11];
    const float* m2_conv_w= (const float*)d_in[12];
    const float* m2_conv_b= (const float*)d_in[13];
    const float* m2_x_w   = (const float*)d_in[14];
    const float* m2_dt_w  = (const float*)d_in[15];
    const float* m2_dt_b  = (const float*)d_in[16];
    const float* m2_A_log = (const float*)d_in[17];
    const float* m2_D     = (const float*)d_in[18];
    const float* m2_out_w = (const float*)d_in[19];
    float* out = (float*)d_out;

    gemm1_mma_kernel<<<dim3(8, 128), 256>>>(fo1, m1_in_w);
    conv_transpose_kernel<<<dim3(16, 128, 4), 256>>>(m1_conv_w, m1_conv_b);
    gemm2_kernel<<<dim3(64, 4), 256>>>(m1_x_w, m1_dt_w, m1_dt_b);
    scanA_kernel<<<1024, 256>>>(m1_A_log);
    scanC_kernel<<<64, 256>>>();
    scanB_kernel<<<1024, 256>>>(m1_A_log, m1_D);
    gemm3t_kernel<<<128, 256>>>(fo2, m1_out_w);
    mamba2_kernel<<<1, 128>>>(m2_in_w, m2_conv_w, m2_conv_b, m2_x_w, m2_dt_w,
                              m2_dt_b, m2_A_log, m2_D, m2_out_w);
    final_kernel<<<2048, 256>>>(out);
}

// round 15
// speedup vs baseline: 1.4649x; 1.0143x over previous
#include <cuda_runtime.h>
#include <cuda_bf16.h>
#include <math.h>
#include <cstdint>

#define Bsz 4
#define Lseq 4096
#define DIN 256
#define DST 16
#define DTR 8
#define NSEG 16
#define SEGL 256   // Lseq / NSEG

// ---------------- scratch ----------------
__device__ __align__(16) float g_xz [Bsz*Lseq*512];      // (b,l,512)
__device__ __align__(16) float g_x  [Bsz*DIN*Lseq];      // post-conv silu, (b,d,l)
__device__ __align__(16) float g_z  [Bsz*DIN*Lseq];      // silu(z) gate, (b,d,l)
__device__ __align__(16) float g_dt [Bsz*DIN*Lseq];      // (b,d,l)
__device__ __align__(16) float g_Bm [Bsz*Lseq*DST];      // (b,l,16)
__device__ __align__(16) float g_Cm [Bsz*Lseq*DST];      // (b,l,16)
__device__ __align__(16) float g_y  [Bsz*DIN*Lseq];      // (b,d,l)
__device__ __align__(16) float g_residual[Bsz*32*Lseq];  // (b,c,h,w)
__device__ __align__(16) float g_segH[Bsz*DIN*NSEG*DST];
__device__ __align__(16) float g_segP[Bsz*DIN*NSEG*DST];
__device__ __align__(16) float g_h0  [Bsz*DIN*NSEG*DST];
__device__ float g_cmean[Bsz*32];
__device__ float g_scale[Bsz*32];

__device__ __forceinline__ float silu_f(float v) { return v / (1.f + __expf(-v)); }
__device__ __forceinline__ float softplus_f(float v) { return (v > 20.f) ? v : log1pf(__expf(v)); }

// ---------------- K1: xz = fop @ in_w^T via mma.sync bf16-split (HMMA) ----------------
__global__ void __launch_bounds__(256) gemm1_mma_kernel(const float* __restrict__ fo1,
                                                        const float* __restrict__ in_w) {
    __shared__ __nv_bfloat16 Ahi[128][36];
    __shared__ __nv_bfloat16 Alo[128][36];
    __shared__ __nv_bfloat16 Bhi[64][36];
    __shared__ __nv_bfloat16 Blo[64][36];
    const int tid = threadIdx.x;
    const int wid = tid >> 5, lane = tid & 31;
    const int bm = blockIdx.y * 128, bn = blockIdx.x * 64;
    const int b = bm >> 12;
    const int wrow = (wid >> 1) * 32;
    const int wcol = (wid & 1) * 32;
    const int r = lane >> 2, q = lane & 3;

    float acc[2][4][4];
    #pragma unroll
    for (int mt = 0; mt < 2; mt++)
        #pragma unroll
        for (int nt = 0; nt < 4; nt++)
            #pragma unroll
            for (int i = 0; i < 4; i++) acc[mt][nt][i] = 0.f;

    for (int k0 = 0; k0 < 128; k0 += 32) {
        #pragma unroll
        for (int it = 0; it < 16; it++) {
            int e = tid + it*256;
            int m = e & 127, kk = e >> 7;
            int j = k0 + kk;
            int g = j >> 5, c = j & 31;
            int l = (bm + m) & 4095;
            int l2 = (g & 1) ? 4095 - l : l;
            int pos = (g < 2) ? l2 : (((l2 & 63) << 6) | (l2 >> 6));
            float v = fo1[((size_t)(b*32 + c))*4096 + pos];
            __nv_bfloat16 h = __float2bfloat16(v);
            Ahi[m][kk] = h;
            Alo[m][kk] = __float2bfloat16(v - __bfloat162float(h));
        }
        #pragma unroll
        for (int it = 0; it < 8; it++) {
            int e = tid + it*256;
            int n = e & 63, kk = e >> 6;
            float v = in_w[(size_t)(bn + n)*128 + k0 + kk];
            __nv_bfloat16 h = __float2bfloat16(v);
            Bhi[n][kk] = h;
            Blo[n][kk] = __float2bfloat16(v - __bfloat162float(h));
        }
        __syncthreads();

        #pragma unroll
        for (int kc = 0; kc < 2; kc++) {
            const int kb = kc*16 + q*2;
            uint32_t ah[2][4], al[2][4], bh[4][2], bl[4][2];
            #pragma unroll
            for (int mt = 0; mt < 2; mt++) {
                int m0 = wrow + mt*16;
                ah[mt][0] = *(const uint32_t*)&Ahi[m0 + r][kb];
                ah[mt][1] = *(const uint32_t*)&Ahi[m0 + r + 8][kb];
                ah[mt][2] = *(const uint32_t*)&Ahi[m0 + r][kb + 8];
                ah[mt][3] = *(const uint32_t*)&Ahi[m0 + r + 8][kb + 8];
                al[mt][0] = *(const uint32_t*)&Alo[m0 + r][kb];
                al[mt][1] = *(const uint32_t*)&Alo[m0 + r + 8][kb];
                al[mt][2] = *(const uint32_t*)&Alo[m0 + r][kb + 8];
                al[mt][3] = *(const uint32_t*)&Alo[m0 + r + 8][kb + 8];
            }
            #pragma unroll
            for (int nt = 0; nt < 4; nt++) {
                int n0 = wcol + nt*8;
                bh[nt][0] = *(const uint32_t*)&Bhi[n0 + r][kb];
                bh[nt][1] = *(const uint32_t*)&Bhi[n0 + r][kb + 8];
                bl[nt][0] = *(const uint32_t*)&Blo[n0 + r][kb];
                bl[nt][1] = *(const uint32_t*)&Blo[n0 + r][kb + 8];
            }
            #pragma unroll
            for (int mt = 0; mt < 2; mt++)
                #pragma unroll
                for (int nt = 0; nt < 4; nt++) {
                    float* c = acc[mt][nt];
                    asm volatile(
                        "mma.sync.aligned.m16n8k16.row.col.f32.bf16.bf16.f32 "
                        "{%0,%1,%2,%3}, {%4,%5,%6,%7}, {%8,%9}, {%0,%1,%2,%3};"
                        : "+f"(c[0]), "+f"(c[1]), "+f"(c[2]), "+f"(c[3])
                        : "r"(ah[mt][0]), "r"(ah[mt][1]), "r"(ah[mt][2]), "r"(ah[mt][3]),
                          "r"(bh[nt][0]), "r"(bh[nt][1]));
                    asm volatile(
                        "mma.sync.aligned.m16n8k16.row.col.f32.bf16.bf16.f32 "
                        "{%0,%1,%2,%3}, {%4,%5,%6,%7}, {%8,%9}, {%0,%1,%2,%3};"
                        : "+f"(c[0]), "+f"(c[1]), "+f"(c[2]), "+f"(c[3])
                        : "r"(ah[mt][0]), "r"(ah[mt][1]), "r"(ah[mt][2]), "r"(ah[mt][3]),
                          "r"(bl[nt][0]), "r"(bl[nt][1]));
                    asm volatile(
                        "mma.sync.aligned.m16n8k16.row.col.f32.bf16.bf16.f32 "
                        "{%0,%1,%2,%3}, {%4,%5,%6,%7}, {%8,%9}, {%0,%1,%2,%3};"
                        : "+f"(c[0]), "+f"(c[1]), "+f"(c[2]), "+f"(c[3])
                        : "r"(al[mt][0]), "r"(al[mt][1]), "r"(al[mt][2]), "r"(al[mt][3]),
                          "r"(bh[nt][0]), "r"(bh[nt][1]));
                }
        }
        __syncthreads();
    }

    #pragma unroll
    for (int mt = 0; mt < 2; mt++) {
        #pragma unroll
        for (int nt = 0; nt < 4; nt++) {
            int row = bm + wrow + mt*16 + r;
            int col = bn + wcol + nt*8 + q*2;
            float* c = acc[mt][nt];
            *(float2*)&g_xz[(size_t)row*512 + col]       = make_float2(c[0], c[1]);
            *(float2*)&g_xz[(size_t)(row + 8)*512 + col] = make_float2(c[2], c[3]);
        }
    }
}

// ---------------- K2: causal depthwise conv(4)+bias+silu; z stored as silu(z) gate ----------------
__global__ void conv_transpose_kernel(const float* __restrict__ conv_w, const float* __restrict__ conv_b) {
    int b = blockIdx.z, lt = blockIdx.y, ct = blockIdx.x;
    int c0 = ct * 32;
    int l0 = lt * 32;
    __shared__ float s[35][33];
    for (int i = threadIdx.x; i < 35*32; i += 256) {
        int li = i >> 5, ci = i & 31;
        int l = l0 - 3 + li;
        s[li][ci] = (l >= 0) ? g_xz[((size_t)b*4096 + l)*512 + c0 + ci] : 0.f;
    }
    __syncthreads();
    int li = threadIdx.x & 31;
    int cw0 = threadIdx.x >> 5;
    if (c0 < 256) {
        for (int ci = cw0; ci < 32; ci += 8) {
            int c = c0 + ci;
            float w0 = conv_w[c*4+0], w1 = conv_w[c*4+1], w2 = conv_w[c*4+2], w3 = conv_w[c*4+3];
            float acc = conv_b[c];
            acc = fmaf(w0, s[li][ci], acc);
            acc = fmaf(w1, s[li+1][ci], acc);
            acc = fmaf(w2, s[li+2][ci], acc);
            acc = fmaf(w3, s[li+3][ci], acc);
            g_x[((size_t)(b*256 + c))*4096 + l0 + li] = silu_f(acc);
        }
    } else {
        for (int ci = cw0; ci < 32; ci += 8) {
            int zc = c0 + ci - 256;
            g_z[((size_t)(b*256 + zc))*4096 + l0 + li] = silu_f(s[li+3][ci]);
        }
    }
}

// ---------------- K3: dbl = x @ x_w^T (N=40) -> B,C + fused dt projection ----------------
__global__ void gemm2_kernel(const float* __restrict__ x_w, const float* __restrict__ dt_w,
                             const float* __restrict__ dt_b) {
    const int b = blockIdx.y;
    const int l0 = blockIdx.x * 64;
    __shared__ float xs[32][66];
    __shared__ float ws[40][33];
    __shared__ float sdtr[64][9];
    __shared__ float sdw[256*8];
    __shared__ float sdb[256];
    const int tid = threadIdx.x;
    const int tcol = tid & 31;
    const int trow = tid >> 5;
    float acc[2][5];
    #pragma unroll
    for (int i = 0; i < 2; i++)
        #pragma unroll
        for (int j = 0; j < 5; j++) acc[i][j] = 0.f;

    for (int i = tid; i < 2048; i += 256) sdw[i] = dt_w[i];
    if (tid < 256) sdb[tid] = dt_b[tid];

    for (int k0 = 0; k0 < 256; k0 += 32) {
        #pragma unroll
        for (int i = tid; i < 2048; i += 256) {
            int kk = i >> 6, lx = i & 63;
            xs[kk][lx] = g_x[((size_t)(b*256 + k0 + kk))*4096 + l0 + lx];
        }
        #pragma unroll
        for (int i = tid; i < 1280; i += 256) {
            int j = i >> 5, kk = i & 31;
            ws[j][kk] = x_w[j*256 + k0 + kk];
        }
        __syncthreads();
        #pragma unroll
        for (int kk = 0; kk < 32; kk++) {
            float2 a = *(const float2*)&xs[kk][tcol*2];
            float w[5];
            #pragma unroll
            for (int jj = 0; jj < 5; jj++) w[jj] = ws[trow*5 + jj][kk];
            #pragma unroll
            for (int jj = 0; jj < 5; jj++) {
                acc[0][jj] = fmaf(a.x, w[jj], acc[0][jj]);
                acc[1][jj] = fmaf(a.y, w[jj], acc[1][jj]);
            }
        }
        __syncthreads();
    }
    #pragma unroll
    for (int i = 0; i < 2; i++) {
        int lx = tcol*2 + i;
        int l = l0 + lx;
        #pragma unroll
        for (int jj = 0; jj < 5; jj++) {
            int j = trow*5 + jj;
            float v = acc[i][jj];
            if (j < 8)       sdtr[lx][j] = v;
            else if (j < 24) g_Bm[((size_t)b*4096 + l)*16 + (j - 8)]  = v;
            else             g_Cm[((size_t)b*4096 + l)*16 + (j - 24)] = v;
        }
    }
    __syncthreads();
    int lx = tid & 63;
    int dg = tid >> 6;
    float r0 = sdtr[lx][0], r1 = sdtr[lx][1], r2 = sdtr[lx][2], r3 = sdtr[lx][3];
    float r4 = sdtr[lx][4], r5 = sdtr[lx][5], r6 = sdtr[lx][6], r7 = sdtr[lx][7];
    #pragma unroll 4
    for (int dd = 0; dd < 64; dd++) {
        int d = dg*64 + dd;
        const float* w = &sdw[d*8];
        float a = sdb[d];
        a = fmaf(r0, w[0], a); a = fmaf(r1, w[1], a);
        a = fmaf(r2, w[2], a); a = fmaf(r3, w[3], a);
        a = fmaf(r4, w[4], a); a = fmaf(r5, w[5], a);
        a = fmaf(r6, w[6], a); a = fmaf(r7, w[7], a);
        g_dt[((size_t)(b*256 + d))*4096 + l0 + lx] = softplus_f(a);
    }
}

// ---------------- K5a: scan pass A ----------------
__global__ void scanA_kernel(const float* __restrict__ A_log) {
    int tid = threadIdx.x;
    int n = tid & 15;
    int task = blockIdx.x * 16 + (tid >> 4);
    int chain = task >> 4;
    int s = task & 15;
    int b = chain >> 8, d = chain & 255;
    int l0 = s * SEGL;
    const float* dtp = g_dt + (size_t)chain*4096 + l0;
    const float* xp  = g_x  + (size_t)chain*4096 + l0;
    const float* Bp  = g_Bm + ((size_t)b*4096 + l0)*16 + n;
    float An = -__expf(A_log[d*16 + n]);
    float h = 0.f, P = 1.f;
    for (int l = 0; l < SEGL; l += 4) {
        float4 dt4 = *(const float4*)(dtp + l);
        float4 x4  = *(const float4*)(xp  + l);
        float dta[4] = {dt4.x, dt4.y, dt4.z, dt4.w};
        float xa [4] = {x4.x,  x4.y,  x4.z,  x4.w};
        #pragma unroll
        for (int i = 0; i < 4; i++) {
            float dt = dta[i];
            float Bv = Bp[(l + i)*16];
            float dA = __expf(dt * An);
            P *= dA;
            h = fmaf(dA, h, dt * xa[i] * Bv);
        }
    }
    g_segH[task*16 + n] = h;
    g_segP[task*16 + n] = P;
}

// ---------------- K5b: combine; zero cmean ----------------
__global__ void scanC_kernel() {
    int t = blockIdx.x * 256 + threadIdx.x;
    if (t < 128) g_cmean[t] = 0.f;
    int chain = t >> 4, n = t & 15;
    float h = 0.f;
    #pragma unroll
    for (int s = 0; s < NSEG; s++) {
        int idx = (chain*16 + s)*16 + n;
        g_h0[idx] = h;
        h = g_segH[idx] + g_segP[idx]*h;
    }
}

// ---------------- K5c: scan pass B ----------------
__global__ void scanB_kernel(const float* __restrict__ A_log, const float* __restrict__ Dp) {
    int tid = threadIdx.x;
    int n = tid & 15;
    int task = blockIdx.x * 16 + (tid >> 4);
    int chain = task >> 4;
    int s = task & 15;
    int b = chain >> 8, d = chain & 255;
    int l0 = s * SEGL;
    const float* dtp = g_dt + (size_t)chain*4096 + l0;
    const float* xp  = g_x  + (size_t)chain*4096 + l0;
    const float* zp  = g_z  + (size_t)chain*4096 + l0;
    const float* Bp  = g_Bm + ((size_t)b*4096 + l0)*16 + n;
    const float* Cp  = g_Cm + ((size_t)b*4096 + l0)*16 + n;
    float* yout = g_y + (size_t)chain*4096 + l0;
    float An = -__expf(A_log[d*16 + n]);
    float Dd = Dp[d];
    float h = g_h0[task*16 + n];
    for (int l = 0; l < SEGL; l += 4) {
        float4 dt4 = *(const float4*)(dtp + l);
        float4 x4  = *(const float4*)(xp  + l);
        float4 z4  = *(const float4*)(zp  + l);
        float dta[4] = {dt4.x, dt4.y, dt4.z, dt4.w};
        float xa [4] = {x4.x,  x4.y,  x4.z,  x4.w};
        float ga [4] = {z4.x,  z4.y,  z4.z,  z4.w};
        float ov[4];
        #pragma unroll
        for (int i = 0; i < 4; i++) {
            float dt = dta[i];
            float Bv = Bp[(l + i)*16];
            float Cv = Cp[(l + i)*16];
            float dA = __expf(dt * An);
            h = fmaf(dA, h, dt * xa[i] * Bv);
            float y = h * Cv;
            y += __shfl_xor_sync(0xFFFFFFFFu, y, 8);
            y += __shfl_xor_sync(0xFFFFFFFFu, y, 4);
            y += __shfl_xor_sync(0xFFFFFFFFu, y, 2);
            y += __shfl_xor_sync(0xFFFFFFFFu, y, 1);
            ov[i] = fmaf(xa[i], Dd, y) * ga[i];
        }
        if (n == 0) {
            *(float4*)(yout + l) = make_float4(ov[0], ov[1], ov[2], ov[3]);
        }
    }
}

// ---------------- K7: res[b,c,l] = (sum_d y[b,d,l]*wsum[c,d]) * fo2[b,c,l]; cmean atomics ----------------
// grid 256 = b*64 ltiles (64 l each).  Block 256 = 32 lcols (2l) x 8 jgroups (4c).
__global__ void gemm3t_kernel(const float* __restrict__ fo2, const float* __restrict__ out_w) {
    int b = blockIdx.x >> 6, lt = blockIdx.x & 63;
    int l0 = lt * 64;
    __shared__ float xs[16][68];
    __shared__ float ws[32][17];
    int tid = threadIdx.x;
    int lcol = tid & 31;       // 2 l each (within-warp lane)
    int jgrp = tid >> 5;       // 4 c each (warp-uniform)
    float acc[2][4];
    #pragma unroll
    for (int i = 0; i < 2; i++)
        #pragma unroll
        for (int j = 0; j < 4; j++) acc[i][j] = 0.f;

    for (int k0 = 0; k0 < 256; k0 += 16) {
        for (int i = tid; i < 1024; i += 256) {
            int di = i >> 6, lx = i & 63;
            xs[di][lx] = g_y[((size_t)(b*256 + k0 + di))*4096 + l0 + lx];
        }
        for (int i = tid; i < 512; i += 256) {
            int j = i >> 4, kk = i & 15;
            int col = k0 + kk;
            ws[j][kk] = out_w[j*256 + col] + out_w[(32 + j)*256 + col]
                      + out_w[(64 + j)*256 + col] + out_w[(96 + j)*256 + col];
        }
        __syncthreads();
        #pragma unroll
        for (int di = 0; di < 16; di++) {
            float2 a = *(const float2*)&xs[di][lcol*2];
            float w[4];
            #pragma unroll
            for (int jj = 0; jj < 4; jj++) w[jj] = ws[jgrp*4 + jj][di];
            #pragma unroll
            for (int jj = 0; jj < 4; jj++) {
                acc[0][jj] = fmaf(a.x, w[jj], acc[0][jj]);
                acc[1][jj] = fmaf(a.y, w[jj], acc[1][jj]);
            }
        }
        __syncthreads();
    }
    #pragma unroll
    for (int jj = 0; jj < 4; jj++) {
        int c = jgrp*4 + jj;
        float s = 0.f;
        #pragma unroll
        for (int i = 0; i < 2; i++) {
            int l = l0 + lcol*2 + i;
            size_t idx = ((size_t)(b*32 + c))*4096 + l;
            float r = acc[i][jj] * fo2[idx];
            g_residual[idx] = r;
            s += r;
        }
        s += __shfl_xor_sync(0xFFFFFFFFu, s, 16);
        s += __shfl_xor_sync(0xFFFFFFFFu, s, 8);
        s += __shfl_xor_sync(0xFFFFFFFFu, s, 4);
        s += __shfl_xor_sync(0xFFFFFFFFu, s, 2);
        s += __shfl_xor_sync(0xFFFFFFFFu, s, 1);
        if (lcol == 0) atomicAdd(&g_cmean[b*32 + c], s);
    }
}

// ---------------- K9: tiny mamba2 ----------------
__global__ void mamba2_kernel(const float* __restrict__ in_w, const float* __restrict__ conv_w,
                              const float* __restrict__ conv_b, const float* __restrict__ x_w,
                              const float* __restrict__ dt_w, const float* __restrict__ dt_b,
                              const float* __restrict__ A_log, const float* __restrict__ Dp,
                              const float* __restrict__ out_w) {
    __shared__ float sxp[4][32][4];
    __shared__ float sx [4][32][4];
    __shared__ float sz [4][32][4];
    __shared__ float sdt[4][32][4];
    __shared__ float sB [4][32][16];
    __shared__ float sC [4][32][16];
    __shared__ float sy [4][32][4];
    int tid = threadIdx.x;
    int b = tid >> 5, l = tid & 31;
    float m0 = g_cmean[b*32 + l] * (1.f/4096.f);
    float m1 = g_cmean[b*32 + 31 - l] * (1.f/4096.f);
    #pragma unroll
    for (int j = 0; j < 4; j++) {
        sxp[b][l][j] = m0*in_w[j*2]       + m1*in_w[j*2 + 1];
        sz [b][l][j] = m0*in_w[(j+4)*2]   + m1*in_w[(j+4)*2 + 1];
    }
    __syncthreads();
    #pragma unroll
    for (int c = 0; c < 4; c++) {
        float acc = conv_b[c];
        #pragma unroll
        for (int t = 0; t < 4; t++) {
            int ls = l - 3 + t;
            float v = (ls >= 0) ? sxp[b][ls][c] : 0.f;
            acc = fmaf(conv_w[c*4 + t], v, acc);
        }
        sx[b][l][c] = acc / (1.f + expf(-acc));
    }
    __syncthreads();
    {
        float xv[4] = {sx[b][l][0], sx[b][l][1], sx[b][l][2], sx[b][l][3]};
        float dtr = 0.f;
        #pragma unroll
        for (int c = 0; c < 4; c++) dtr = fmaf(xv[c], x_w[c], dtr);
        #pragma unroll
        for (int n = 0; n < 16; n++) {
            float bb = 0.f, cc = 0.f;
            #pragma unroll
            for (int c = 0; c < 4; c++) {
                bb = fmaf(xv[c], x_w[(1 + n)*4 + c], bb);
                cc = fmaf(xv[c], x_w[(17 + n)*4 + c], cc);
            }
            sB[b][l][n] = bb;
            sC[b][l][n] = cc;
        }
        #pragma unroll
        for (int dd = 0; dd < 4; dd++) {
            float a = fmaf(dtr, dt_w[dd], dt_b[dd]);
            sdt[b][l][dd] = (a > 20.f) ? a : log1pf(expf(a));
        }
    }
    __syncthreads();
    {
        int lane = tid & 31, wb = tid >> 5;
        int grp = lane >> 4, n = lane & 15;
        int d0 = grp, d1 = grp + 2;
        float A0 = -expf(A_log[d0*16 + n]);
        float A1 = -expf(A_log[d1*16 + n]);
        float h0 = 0.f, h1 = 0.f;
        for (int t = 0; t < 32; t++) {
            float Bv = sB[wb][t][n], Cv = sC[wb][t][n];
            float dt0 = sdt[wb][t][d0], x0 = sx[wb][t][d0];
            float dt1 = sdt[wb][t][d1], x1 = sx[wb][t][d1];
            h0 = fmaf(__expf(dt0*A0), h0, dt0*x0*Bv);
            h1 = fmaf(__expf(dt1*A1), h1, dt1*x1*Bv);
            float y0 = h0*Cv, y1 = h1*Cv;
            y0 += __shfl_xor_sync(0xFFFFFFFFu, y0, 8);
            y0 += __shfl_xor_sync(0xFFFFFFFFu, y0, 4);
            y0 += __shfl_xor_sync(0xFFFFFFFFu, y0, 2);
            y0 += __shfl_xor_sync(0xFFFFFFFFu, y0, 1);
            y1 += __shfl_xor_sync(0xFFFFFFFFu, y1, 8);
            y1 += __shfl_xor_sync(0xFFFFFFFFu, y1, 4);
            y1 += __shfl_xor_sync(0xFFFFFFFFu, y1, 2);
            y1 += __shfl_xor_sync(0xFFFFFFFFu, y1, 1);
            if (n == 0) { sy[wb][t][d0] = y0; sy[wb][t][d1] = y1; }
        }
    }
    __syncthreads();
    {
        float scale = 0.f;
        #pragma unroll
        for (int dd = 0; dd < 4; dd++) {
            float yv = fmaf(sx[b][l][dd], Dp[dd], sy[b][l][dd]);
            float zz = sz[b][l][dd];
            yv *= zz / (1.f + expf(-zz));
            scale = fmaf(yv, out_w[dd] + out_w[4 + dd], scale);
        }
        g_scale[b*32 + l] = scale;
    }
}

// ---------------- K10: out = residual * (scale + 1) ----------------
__global__ void final_kernel(float* __restrict__ out) {
    int idx = blockIdx.x * 256 + threadIdx.x;
    out[idx] = g_residual[idx] * (g_scale[idx >> 12] + 1.f);
}

// ---------------- launch ----------------
extern "C" void kernel_launch(void* const* d_in, const int* in_sizes, int n_in,
                              void* d_out, int out_size) {
    const float* fo1      = (const float*)d_in[0];
    const float* fo2      = (const float*)d_in[1];
    const float* m1_in_w  = (const float*)d_in[2];
    const float* m1_conv_w= (const float*)d_in[3];
    const float* m1_conv_b= (const float*)d_in[4];
    const float* m1_x_w   = (const float*)d_in[5];
    const float* m1_dt_w  = (const float*)d_in[6];
    const float* m1_dt_b  = (const float*)d_in[7];
    const float* m1_A_log = (const float*)d_in[8];
    const float* m1_D     = (const float*)d_in[9];
    const float* m1_out_w = (const float*)d_in[10];
    const float* m2_in_w  = (const float*)d_in[11];
    const float* m2_conv_w= (const float*)d_in[12];
    const float* m2_conv_b= (const float*)d_in[13];
    const float* m2_x_w   = (const float*)d_in[14];
    const float* m2_dt_w  = (const float*)d_in[15];
    const float* m2_dt_b  = (const float*)d_in[16];
    const float* m2_A_log = (const float*)d_in[17];
    const float* m2_D     = (const float*)d_in[18];
    const float* m2_out_w = (const float*)d_in[19];
    float* out = (float*)d_out;

    gemm1_mma_kernel<<<dim3(8, 128), 256>>>(fo1, m1_in_w);
    conv_transpose_kernel<<<dim3(16, 128, 4), 256>>>(m1_conv_w, m1_conv_b);
    gemm2_kernel<<<dim3(64, 4), 256>>>(m1_x_w, m1_dt_w, m1_dt_b);
    scanA_kernel<<<1024, 256>>>(m1_A_log);
    scanC_kernel<<<64, 256>>>();
    scanB_kernel<<<1024, 256>>>(m1_A_log, m1_D);
    gemm3t_kernel<<<256, 256>>>(fo2, m1_out_w);
    mamba2_kernel<<<1, 128>>>(m2_in_w, m2_conv_w, m2_conv_b, m2_x_w, m2_dt_w,
                              m2_dt_b, m2_A_log, m2_D, m2_out_w);
    final_kernel<<<2048, 256>>>(out);
}